// round 5
// baseline (speedup 1.0000x reference)
#include <cuda_runtime.h>
#include <cstdint>
#include <math.h>

#define T_ 256
#define B_ 128
#define H_ 1024
#define L_ 4
#define TB_ (T_ * B_)        /* 32768 */
#define BH_ (B_ * H_)        /* 131072 */
#define TBH_ (T_ * B_ * H_)  /* 33554432 */
#define LHH_ (L_ * H_ * H_)  /* 4194304 */

#define REC_CTAS 128         /* <= 148 so all CTAs co-resident */

// Full-sequence ping-pong scratch + pre-split tf32 weights. Allocation-free.
__device__ float g_seq0[TBH_];
__device__ float g_seq1[TBH_];
__device__ float g_Uhi[LHH_];   // W_ih hi (tf32-rounded fp32 bits)
__device__ float g_Ulo[LHH_];   // W_ih lo
__device__ float g_Whi[LHH_];   // W_hh hi
__device__ float g_Wlo[LHH_];   // W_hh lo

// Grid-barrier state.
__device__ unsigned int g_cnt = 0;
__device__ unsigned int g_gen = 0;

// ===========================================================================
// tf32 helpers (baseline PTX, no sm_103a-only features)
// ===========================================================================
__device__ __forceinline__ uint32_t f2tf32(float x) {
    uint32_t r;
    asm("cvt.rna.tf32.f32 %0, %1;" : "=r"(r) : "f"(x));
    return r;
}
__device__ __forceinline__ void split_tf32(float x, uint32_t& hi, uint32_t& lo) {
    hi = f2tf32(x);
    lo = f2tf32(x - __uint_as_float(hi));
}
// D += A(16x8,row) * B(8x8,col): tf32 inputs, f32 accumulate.
__device__ __forceinline__ void mma8(float* d, const uint32_t* a, uint32_t b0, uint32_t b1) {
    asm volatile("mma.sync.aligned.m16n8k8.row.col.f32.tf32.tf32.f32 "
                 "{%0,%1,%2,%3}, {%4,%5,%6,%7}, {%8,%9}, {%0,%1,%2,%3};"
                 : "+f"(d[0]), "+f"(d[1]), "+f"(d[2]), "+f"(d[3])
                 : "r"(a[0]), "r"(a[1]), "r"(a[2]), "r"(a[3]), "r"(b0), "r"(b1));
}

// ===========================================================================
// One-time weight split: W -> (tf32 hi, tf32 lo) for both W_ih and W_hh.
// ===========================================================================
__global__ __launch_bounds__(256)
void split_kernel(const float* __restrict__ Wih, const float* __restrict__ Whh)
{
    const size_t i = (size_t)blockIdx.x * 256 + threadIdx.x;   // < LHH_
    uint32_t hi, lo;
    split_tf32(Wih[i], hi, lo);
    g_Uhi[i] = __uint_as_float(hi); g_Ulo[i] = __uint_as_float(lo);
    split_tf32(Whh[i], hi, lo);
    g_Whi[i] = __uint_as_float(hi); g_Wlo[i] = __uint_as_float(lo);
}

// ===========================================================================
// Input projection (3xTF32 warp-mma):
//   out[m, n] = sum_k X[m,k] * W[n,k] + bi[n] + bh[n]
// M=32768, N=1024, K=1024. Grid (16 n-tiles, 256 m-tiles), 256 thr.
// CTA tile BM=128 (8 warps x m16), BN=64 (4 x n16 per warp).
// ===========================================================================
__global__ __launch_bounds__(256)
void proj_mma_kernel(const float* __restrict__ X,
                     const float* __restrict__ Whi,
                     const float* __restrict__ Wlo,
                     const float* __restrict__ bi,
                     const float* __restrict__ bh,
                     float* __restrict__ out)
{
    const int tid  = threadIdx.x;
    const int wid  = tid >> 5;
    const int lane = tid & 31;
    const int grp  = lane >> 2;   // 0..7
    const int qid  = lane & 3;    // 0..3
    const int m0 = blockIdx.y * 128 + wid * 16;
    const int n0 = blockIdx.x * 64;

    // a0=(grp,k+qid) a1=(grp+8,k+qid) a2=(grp,k+qid+4) a3=(grp+8,k+qid+4)
    const float* Arow  = X   + (size_t)(m0 + grp) * H_ + qid;
    const float* BHrow = Whi + (size_t)(n0 + grp) * H_ + qid;
    const float* BLrow = Wlo + (size_t)(n0 + grp) * H_ + qid;

    float acc[4][2][4];
#pragma unroll
    for (int c = 0; c < 4; c++)
#pragma unroll
        for (int n8 = 0; n8 < 2; n8++)
#pragma unroll
            for (int i = 0; i < 4; i++) acc[c][n8][i] = 0.0f;

#pragma unroll 2
    for (int kt = 0; kt < H_; kt += 8) {
        const float a0 = Arow[kt];
        const float a1 = Arow[(size_t)8 * H_ + kt];
        const float a2 = Arow[kt + 4];
        const float a3 = Arow[(size_t)8 * H_ + kt + 4];
        uint32_t ah[4], al[4];
        split_tf32(a0, ah[0], al[0]);
        split_tf32(a1, ah[1], al[1]);
        split_tf32(a2, ah[2], al[2]);
        split_tf32(a3, ah[3], al[3]);
#pragma unroll
        for (int c = 0; c < 4; c++) {
#pragma unroll
            for (int n8 = 0; n8 < 2; n8++) {
                const size_t off = (size_t)(c * 16 + n8 * 8) * H_ + kt;
                const uint32_t bh0 = __float_as_uint(BHrow[off]);
                const uint32_t bh1 = __float_as_uint(BHrow[off + 4]);
                const uint32_t bl0 = __float_as_uint(BLrow[off]);
                const uint32_t bl1 = __float_as_uint(BLrow[off + 4]);
                mma8(acc[c][n8], ah, bh0, bh1);
                mma8(acc[c][n8], ah, bl0, bl1);
                mma8(acc[c][n8], al, bh0, bh1);
            }
        }
    }

    // Epilogue: c0/c1 -> (row grp, cols 2q,2q+1); c2/c3 -> row grp+8.
#pragma unroll
    for (int c = 0; c < 4; c++) {
#pragma unroll
        for (int n8 = 0; n8 < 2; n8++) {
            const int col = n0 + c * 16 + n8 * 8 + 2 * qid;
            const float2 v1 = *(const float2*)(bi + col);
            const float2 v2 = *(const float2*)(bh + col);
            const float bx = v1.x + v2.x, by = v1.y + v2.y;
            float* o0 = out + (size_t)(m0 + grp) * H_ + col;
            float* o1 = out + (size_t)(m0 + grp + 8) * H_ + col;
            float2 r0 = { acc[c][n8][0] + bx, acc[c][n8][1] + by };
            float2 r1 = { acc[c][n8][2] + bx, acc[c][n8][3] + by };
            *(float2*)o0 = r0;
            *(float2*)o1 = r1;
        }
    }
}

// ===========================================================================
// Persistent recurrence (3xTF32 warp-mma), W-stripe resident in smem.
// Grid (64 n-tiles, 2 m-tiles) = 128 CTAs, 128 thr (4 warps x m16).
// CTA tile BM=64, BN=16; W rows [n0, n0+16) (hi+lo) cached k-major in smem
// for all 256 steps. Step t: Y[t] = tanh(Y[t] + h_{t-1} @ Wh^T).
// ===========================================================================
__device__ __forceinline__ void rec_loadA(float* r, const float* A0, int koff)
{
#pragma unroll
    for (int kk = 0; kk < 4; kk++) {
        const float* b = A0 + koff + kk * 8;
        r[kk * 4 + 0] = b[0];
        r[kk * 4 + 1] = b[(size_t)8 * H_];
        r[kk * 4 + 2] = b[4];
        r[kk * 4 + 3] = b[(size_t)8 * H_ + 4];
    }
}

__device__ __forceinline__ void rec_proc(const float* raw, int kbase,
                                         const float* sBhi, const float* sBlo,
                                         int grp, int qid,
                                         float* acc0, float* acc1)
{
#pragma unroll
    for (int kk = 0; kk < 4; kk++) {
        const int kt = kbase + kk * 8;
        uint32_t ah[4], al[4];
        split_tf32(raw[kk * 4 + 0], ah[0], al[0]);
        split_tf32(raw[kk * 4 + 1], ah[1], al[1]);
        split_tf32(raw[kk * 4 + 2], ah[2], al[2]);
        split_tf32(raw[kk * 4 + 3], ah[3], al[3]);
        const int kb = (kt + qid) * 16;
        const uint32_t bh0a = __float_as_uint(sBhi[kb + grp]);
        const uint32_t bh0b = __float_as_uint(sBhi[kb + 64 + grp]);
        const uint32_t bh1a = __float_as_uint(sBhi[kb + 8 + grp]);
        const uint32_t bh1b = __float_as_uint(sBhi[kb + 72 + grp]);
        const uint32_t bl0a = __float_as_uint(sBlo[kb + grp]);
        const uint32_t bl0b = __float_as_uint(sBlo[kb + 64 + grp]);
        const uint32_t bl1a = __float_as_uint(sBlo[kb + 8 + grp]);
        const uint32_t bl1b = __float_as_uint(sBlo[kb + 72 + grp]);
        mma8(acc0, ah, bh0a, bh0b);
        mma8(acc0, ah, bl0a, bl0b);
        mma8(acc0, al, bh0a, bh0b);
        mma8(acc1, ah, bh1a, bh1b);
        mma8(acc1, ah, bl1a, bl1b);
        mma8(acc1, al, bh1a, bh1b);
    }
}

__global__ __launch_bounds__(128)
void recur_mma_kernel(const float* __restrict__ hx,
                      const float* __restrict__ Whi,
                      const float* __restrict__ Wlo,
                      float* __restrict__ Y,
                      float* __restrict__ hn)
{
    extern __shared__ float sB[];        // [0,16384): hi k-major, [16384,32768): lo
    float* sBhi = sB;
    float* sBlo = sB + 16384;
    __shared__ unsigned int s_gen;

    const int tid  = threadIdx.x;
    const int wid  = tid >> 5;
    const int lane = tid & 31;
    const int grp  = lane >> 2;
    const int qid  = lane & 3;
    const int n0 = blockIdx.x * 16;
    const int m0 = blockIdx.y * 64 + wid * 16;

    // Stage this CTA's W stripe (16 rows, full K) into smem, k-major [k][n].
    {
        const int r   = tid >> 3;        // 0..15  (row within stripe)
        const int seg = tid & 7;         // 0..7   (128-col segment)
        const float* src_h = Whi + (size_t)(n0 + r) * H_ + seg * 128;
        const float* src_l = Wlo + (size_t)(n0 + r) * H_ + seg * 128;
        for (int j = 0; j < 128; j += 4) {
            const float4 h4 = *(const float4*)(src_h + j);
            const float4 l4 = *(const float4*)(src_l + j);
            const int k = seg * 128 + j;
            sBhi[(k + 0) * 16 + r] = h4.x; sBhi[(k + 1) * 16 + r] = h4.y;
            sBhi[(k + 2) * 16 + r] = h4.z; sBhi[(k + 3) * 16 + r] = h4.w;
            sBlo[(k + 0) * 16 + r] = l4.x; sBlo[(k + 1) * 16 + r] = l4.y;
            sBlo[(k + 2) * 16 + r] = l4.z; sBlo[(k + 3) * 16 + r] = l4.w;
        }
    }
    if (tid == 0) s_gen = *(volatile unsigned int*)&g_gen;
    __syncthreads();
    const unsigned int gen0 = s_gen;

    for (int t = 0; t < T_; t++) {
        const float* hp = t ? (Y + (size_t)(t - 1) * BH_) : hx;
        const float* A0 = hp + (size_t)(m0 + grp) * H_ + qid;
        float* yt = Y + (size_t)t * BH_;

        float acc0[4] = {0.f, 0.f, 0.f, 0.f};
        float acc1[4] = {0.f, 0.f, 0.f, 0.f};
        float ra[16], rb[16];

        rec_loadA(ra, A0, 0);
#pragma unroll 1
        for (int c = 0; c < 32; c += 2) {
            rec_loadA(rb, A0, (c + 1) * 32);
            rec_proc(ra, c * 32, sBhi, sBlo, grp, qid, acc0, acc1);
            if (c + 2 < 32) rec_loadA(ra, A0, (c + 2) * 32);
            rec_proc(rb, (c + 1) * 32, sBhi, sBlo, grp, qid, acc0, acc1);
        }

        // Epilogue: in-place add of precomputed projection + tanh.
#pragma unroll
        for (int n8 = 0; n8 < 2; n8++) {
            const float* ac = n8 ? acc1 : acc0;
            const int col = n0 + n8 * 8 + 2 * qid;
            float* p0 = yt + (size_t)(m0 + grp) * H_ + col;
            float* p1 = yt + (size_t)(m0 + grp + 8) * H_ + col;
            const float2 x0 = *(const float2*)p0;
            const float2 x1 = *(const float2*)p1;
            float2 v0 = { tanhf(ac[0] + x0.x), tanhf(ac[1] + x0.y) };
            float2 v1 = { tanhf(ac[2] + x1.x), tanhf(ac[3] + x1.y) };
            *(float2*)p0 = v0;
            *(float2*)p1 = v1;
            if (t == T_ - 1) {
                *(float2*)(hn + (size_t)(m0 + grp) * H_ + col) = v0;
                *(float2*)(hn + (size_t)(m0 + grp + 8) * H_ + col) = v1;
            }
        }

        // Grid barrier (not needed after the last step).
        if (t < T_ - 1) {
            __syncthreads();
            if (tid == 0) {
                __threadfence();
                const unsigned int old = atomicAdd(&g_cnt, 1u);
                if (old == REC_CTAS - 1) {
                    atomicExch(&g_cnt, 0u);
                    __threadfence();
                    atomicAdd(&g_gen, 1u);
                } else {
                    const unsigned int target = gen0 + (unsigned int)t + 1u;
                    while (*(volatile unsigned int*)&g_gen < target) __nanosleep(64);
                }
                __threadfence();
            }
            __syncthreads();
        }
    }
}

// ===========================================================================
extern "C" void kernel_launch(void* const* d_in, const int* in_sizes, int n_in,
                              void* d_out, int out_size)
{
    const float* inputs = (const float*)d_in[0];
    const float* hxs    = (const float*)d_in[1];
    const float* W_ih   = (const float*)d_in[2];
    const float* b_ih   = (const float*)d_in[3];
    const float* W_hh   = (const float*)d_in[4];
    const float* b_hh   = (const float*)d_in[5];
    float* out = (float*)d_out;

    float *seq0, *seq1, *uhi, *ulo, *whi, *wlo;
    cudaGetSymbolAddress((void**)&seq0, g_seq0);
    cudaGetSymbolAddress((void**)&seq1, g_seq1);
    cudaGetSymbolAddress((void**)&uhi, g_Uhi);
    cudaGetSymbolAddress((void**)&ulo, g_Ulo);
    cudaGetSymbolAddress((void**)&whi, g_Whi);
    cudaGetSymbolAddress((void**)&wlo, g_Wlo);

    cudaFuncSetAttribute(recur_mma_kernel,
                         cudaFuncAttributeMaxDynamicSharedMemorySize, 131072);

    const float* layer_in[L_]  = { inputs, seq0, seq1, seq0 };
    float*       layer_out[L_] = { seq0, seq1, seq0, out };

    // Pre-split all weights into tf32 hi/lo pairs.
    split_kernel<<<LHH_ / 256, 256>>>(W_ih, W_hh);

    const dim3 proj_grid(H_ / 64, TB_ / 128);   // (16, 256)
    const dim3 rec_grid(H_ / 16, B_ / 64);      // (64, 2) = 128 CTAs

    for (int l = 0; l < L_; l++) {
        const float* X = layer_in[l];
        float* Y = layer_out[l];
        const size_t wo = (size_t)l * H_ * H_;

        proj_mma_kernel<<<proj_grid, 256>>>(X, uhi + wo, ulo + wo,
                                            b_ih + (size_t)l * H_,
                                            b_hh + (size_t)l * H_, Y);

        recur_mma_kernel<<<rec_grid, 128, 131072>>>(hxs + (size_t)l * BH_,
                                                    whi + wo, wlo + wo, Y,
                                                    out + (size_t)TBH_ + (size_t)l * BH_);
    }
}

// round 6
// speedup vs baseline: 2.6991x; 2.6991x over previous
#include <cuda_runtime.h>
#include <cuda_bf16.h>
#include <cstdint>
#include <math.h>

#define T_ 256
#define B_ 128
#define H_ 1024
#define H2 512                    /* H/2 packed u32 pairs */
#define L_ 4
#define TB_ 32768
#define BH_ 131072
#define TBH_ 33554432
#define LHH2 (L_ * H_ * H2)       /* 2097152 */

#define REC_CTAS 128

// ---------------------------------------------------------------------------
// Device globals (allocation-free scratch)
// ---------------------------------------------------------------------------
__device__ float g_P[TBH_];                       // proj results (fp32), reused per layer
__device__ uint32_t g_xhi0[TB_ * H2];             // activation planes, ping
__device__ uint32_t g_xlo0[TB_ * H2];
__device__ uint32_t g_xhi1[TB_ * H2];             // activation planes, pong
__device__ uint32_t g_xlo1[TB_ * H2];
__device__ uint32_t g_uihi[LHH2], g_uilo[LHH2];   // W_ih planes (packed bf16 pairs)
__device__ uint32_t g_whhi[LHH2], g_whlo[LHH2];   // W_hh planes
__device__ uint32_t g_hxhi[L_ * B_ * H2], g_hxlo[L_ * B_ * H2];
__device__ unsigned int g_cnt = 0, g_gen = 0;

// ---------------------------------------------------------------------------
// Helpers
// ---------------------------------------------------------------------------
__device__ __forceinline__ void splitpack(float x0, float x1, uint32_t& hi, uint32_t& lo) {
    __nv_bfloat16 h0 = __float2bfloat16(x0);
    __nv_bfloat16 h1 = __float2bfloat16(x1);
    __nv_bfloat16 l0 = __float2bfloat16(x0 - __bfloat162float(h0));
    __nv_bfloat16 l1 = __float2bfloat16(x1 - __bfloat162float(h1));
    hi = (uint32_t)__bfloat16_as_ushort(h0) | ((uint32_t)__bfloat16_as_ushort(h1) << 16);
    lo = (uint32_t)__bfloat16_as_ushort(l0) | ((uint32_t)__bfloat16_as_ushort(l1) << 16);
}
// D += A(16x16) * B(16x8), bf16 in, f32 accum
__device__ __forceinline__ void mma16(float* d, const uint32_t* a, uint32_t b0, uint32_t b1) {
    asm volatile("mma.sync.aligned.m16n8k16.row.col.f32.bf16.bf16.f32 "
                 "{%0,%1,%2,%3}, {%4,%5,%6,%7}, {%8,%9}, {%0,%1,%2,%3};"
                 : "+f"(d[0]), "+f"(d[1]), "+f"(d[2]), "+f"(d[3])
                 : "r"(a[0]), "r"(a[1]), "r"(a[2]), "r"(a[3]), "r"(b0), "r"(b1));
}
__device__ __forceinline__ float fast_tanh(float x) {
    const float e = __expf(2.0f * x);
    return 1.0f - __fdividef(2.0f, e + 1.0f);
}

// ---------------------------------------------------------------------------
// One-time splits
// ---------------------------------------------------------------------------
__global__ __launch_bounds__(256)
void split_w_kernel(const float* __restrict__ Wih, const float* __restrict__ Whh)
{
    const size_t i = (size_t)blockIdx.x * 256 + threadIdx.x;   // < LHH2
    uint32_t hi, lo;
    splitpack(Wih[2 * i], Wih[2 * i + 1], hi, lo);
    g_uihi[i] = hi; g_uilo[i] = lo;
    splitpack(Whh[2 * i], Whh[2 * i + 1], hi, lo);
    g_whhi[i] = hi; g_whlo[i] = lo;
}
__global__ __launch_bounds__(256)
void split_x_kernel(const float* __restrict__ X)
{
    const size_t i = (size_t)blockIdx.x * 256 + threadIdx.x;   // < TB_*H2
    uint32_t hi, lo;
    splitpack(X[2 * i], X[2 * i + 1], hi, lo);
    g_xhi0[i] = hi; g_xlo0[i] = lo;
}
__global__ __launch_bounds__(256)
void split_hx_kernel(const float* __restrict__ hx)
{
    const size_t i = (size_t)blockIdx.x * 256 + threadIdx.x;   // < L_*B_*H2
    uint32_t hi, lo;
    splitpack(hx[2 * i], hx[2 * i + 1], hi, lo);
    g_hxhi[i] = hi; g_hxlo[i] = lo;
}

// ---------------------------------------------------------------------------
// Input projection: P[m,n] = sum_k X[m,k]*W[n,k] + bi[n] + bh[n]
// M=32768, N=1024, K=1024. CTA 128x64, BK=32 elems (16 u32). 256 thr, 8 warps
// (4m x 2n), warp tile m32 x n32. Operands smem-staged, padded stride 20 u32.
// ---------------------------------------------------------------------------
#define P_STR 20
#define P_SAHI 0
#define P_SALO 2560
#define P_SBHI 5120
#define P_SBLO 6400
#define P_SMEM_BYTES (7680u * 4u)

__global__ __launch_bounds__(256, 2)
void proj_kernel(const uint32_t* __restrict__ Xhi, const uint32_t* __restrict__ Xlo,
                 const uint32_t* __restrict__ Whi_, const uint32_t* __restrict__ Wlo_,
                 const float* __restrict__ bi, const float* __restrict__ bhh,
                 float* __restrict__ P)
{
    extern __shared__ uint32_t sm[];
    const int tid = threadIdx.x, wid = tid >> 5, lane = tid & 31;
    const int grp = lane >> 2, qid = lane & 3;
    const int m0 = blockIdx.y * 128, n0 = blockIdx.x * 64;
    const int wm = (wid >> 1) * 32, wn = (wid & 1) * 32;

    const int arow = tid >> 1, acg = (tid & 1) * 8;    // A: 128 rows x 16 u32
    const int brow = tid >> 2, bcg = (tid & 3) * 4;    // B: 64 rows x 16 u32

    const uint32_t* Ah = Xhi  + (size_t)(m0 + arow) * H2 + acg;
    const uint32_t* Al = Xlo  + (size_t)(m0 + arow) * H2 + acg;
    const uint32_t* Bh = Whi_ + (size_t)(n0 + brow) * H2 + bcg;
    const uint32_t* Bl = Wlo_ + (size_t)(n0 + brow) * H2 + bcg;

    float acc[2][4][4];
#pragma unroll
    for (int mt = 0; mt < 2; mt++)
#pragma unroll
        for (int nt = 0; nt < 4; nt++)
#pragma unroll
            for (int i = 0; i < 4; i++) acc[mt][nt][i] = 0.0f;

    uint4 rah0 = *(const uint4*)Ah,       rah1 = *(const uint4*)(Ah + 4);
    uint4 ral0 = *(const uint4*)Al,       ral1 = *(const uint4*)(Al + 4);
    uint4 rbh  = *(const uint4*)Bh,       rbl  = *(const uint4*)Bl;

    for (int kb2 = 0; kb2 < H2; kb2 += 16) {
        __syncthreads();
        *(uint4*)&sm[P_SAHI + arow * P_STR + acg]     = rah0;
        *(uint4*)&sm[P_SAHI + arow * P_STR + acg + 4] = rah1;
        *(uint4*)&sm[P_SALO + arow * P_STR + acg]     = ral0;
        *(uint4*)&sm[P_SALO + arow * P_STR + acg + 4] = ral1;
        *(uint4*)&sm[P_SBHI + brow * P_STR + bcg]     = rbh;
        *(uint4*)&sm[P_SBLO + brow * P_STR + bcg]     = rbl;
        __syncthreads();
        if (kb2 + 16 < H2) {
            rah0 = *(const uint4*)(Ah + kb2 + 16); rah1 = *(const uint4*)(Ah + kb2 + 20);
            ral0 = *(const uint4*)(Al + kb2 + 16); ral1 = *(const uint4*)(Al + kb2 + 20);
            rbh  = *(const uint4*)(Bh + kb2 + 16); rbl  = *(const uint4*)(Bl + kb2 + 16);
        }
#pragma unroll
        for (int kk = 0; kk < 2; kk++) {
            const int kb8 = kk * 8;
            uint32_t ah[2][4], al[2][4];
#pragma unroll
            for (int mt = 0; mt < 2; mt++) {
                const int r = wm + mt * 16;
                ah[mt][0] = sm[P_SAHI + (r + grp)     * P_STR + kb8 + qid];
                ah[mt][1] = sm[P_SAHI + (r + grp + 8) * P_STR + kb8 + qid];
                ah[mt][2] = sm[P_SAHI + (r + grp)     * P_STR + kb8 + qid + 4];
                ah[mt][3] = sm[P_SAHI + (r + grp + 8) * P_STR + kb8 + qid + 4];
                al[mt][0] = sm[P_SALO + (r + grp)     * P_STR + kb8 + qid];
                al[mt][1] = sm[P_SALO + (r + grp + 8) * P_STR + kb8 + qid];
                al[mt][2] = sm[P_SALO + (r + grp)     * P_STR + kb8 + qid + 4];
                al[mt][3] = sm[P_SALO + (r + grp + 8) * P_STR + kb8 + qid + 4];
            }
#pragma unroll
            for (int nt = 0; nt < 4; nt++) {
                const int br = wn + nt * 8 + grp;
                const uint32_t bh0 = sm[P_SBHI + br * P_STR + kb8 + qid];
                const uint32_t bh1 = sm[P_SBHI + br * P_STR + kb8 + qid + 4];
                const uint32_t bl0 = sm[P_SBLO + br * P_STR + kb8 + qid];
                const uint32_t bl1 = sm[P_SBLO + br * P_STR + kb8 + qid + 4];
#pragma unroll
                for (int mt = 0; mt < 2; mt++) {
                    mma16(acc[mt][nt], ah[mt], bh0, bh1);
                    mma16(acc[mt][nt], ah[mt], bl0, bl1);
                    mma16(acc[mt][nt], al[mt], bh0, bh1);
                }
            }
        }
    }

#pragma unroll
    for (int mt = 0; mt < 2; mt++) {
#pragma unroll
        for (int nt = 0; nt < 4; nt++) {
            const int col = n0 + wn + nt * 8 + 2 * qid;
            const float bx = bi[col] + bhh[col];
            const float by = bi[col + 1] + bhh[col + 1];
            const int r0 = m0 + wm + mt * 16 + grp;
            float2 v0 = { acc[mt][nt][0] + bx, acc[mt][nt][1] + by };
            float2 v1 = { acc[mt][nt][2] + bx, acc[mt][nt][3] + by };
            *(float2*)&P[(size_t)r0 * H_ + col] = v0;
            *(float2*)&P[(size_t)(r0 + 8) * H_ + col] = v1;
        }
    }
}

// ---------------------------------------------------------------------------
// Persistent recurrence. Grid (32 n-tiles, 4 m-tiles) = 128 CTAs, 128 thr
// (4 warps: 2m x 2n, warp tile m16 x n16). W stripe (32 rows, hi+lo) resident
// in smem for all 256 steps; A double-buffered (BK=64) with reg prefetch.
// Epilogue: h = tanh(acc + P), writes packed planes (+ fp32 out for last layer).
// ---------------------------------------------------------------------------
#define R_WSTR 516
#define R_ASTR 36
#define R_WHI 0
#define R_WLO 16512
#define R_ABUF 33024
#define R_ABUFSZ 2304            /* hi 1152 + lo 1152 */
#define R_SMEM_BYTES ((33024u + 4608u) * 4u)   /* 150528 */

__global__ __launch_bounds__(128, 1)
void recur_kernel(const uint32_t* __restrict__ hxhi, const uint32_t* __restrict__ hxlo,
                  const uint32_t* __restrict__ Whi_, const uint32_t* __restrict__ Wlo_,
                  const float* __restrict__ P,
                  uint32_t* __restrict__ pohi, uint32_t* __restrict__ polo,
                  float* __restrict__ Yout,          // non-null only for last layer
                  float* __restrict__ hn)
{
    extern __shared__ uint32_t sm[];
    __shared__ unsigned int s_gen;

    const int tid = threadIdx.x, wid = tid >> 5, lane = tid & 31;
    const int grp = lane >> 2, qid = lane & 3;
    const int n0 = blockIdx.x * 32, m0 = blockIdx.y * 32;
    const int wm = (wid >> 1) * 16, wn = (wid & 1) * 16;

    // Stage W stripe (32 rows x 512 u32 per plane) into padded smem.
    for (int idx = tid * 4; idx < 32 * H2; idx += 128 * 4) {
        const int r = idx >> 9, c = idx & (H2 - 1);
        *(uint4*)&sm[R_WHI + r * R_WSTR + c] = *(const uint4*)&Whi_[(size_t)(n0 + r) * H2 + c];
        *(uint4*)&sm[R_WLO + r * R_WSTR + c] = *(const uint4*)&Wlo_[(size_t)(n0 + r) * H2 + c];
    }
    if (tid == 0) s_gen = *(volatile unsigned int*)&g_gen;
    __syncthreads();
    const unsigned int gen0 = s_gen;

    const int lrow = tid >> 2, lcg = (tid & 3) * 8;    // A loader: 32 rows x 32 u32

    for (int t = 0; t < T_; t++) {
        const uint32_t* Ahp = t ? (pohi + (size_t)(t - 1) * (B_ * H2)) : hxhi;
        const uint32_t* Alp = t ? (polo + (size_t)(t - 1) * (B_ * H2)) : hxlo;
        const uint32_t* Ah = Ahp + (size_t)(m0 + lrow) * H2 + lcg;
        const uint32_t* Al = Alp + (size_t)(m0 + lrow) * H2 + lcg;

        float acc[2][4];
#pragma unroll
        for (int nt = 0; nt < 2; nt++)
#pragma unroll
            for (int i = 0; i < 4; i++) acc[nt][i] = 0.0f;

        uint4 rh0 = *(const uint4*)Ah, rh1 = *(const uint4*)(Ah + 4);
        uint4 rl0 = *(const uint4*)Al, rl1 = *(const uint4*)(Al + 4);
        {
            uint32_t* b = &sm[R_ABUF];
            *(uint4*)&b[lrow * R_ASTR + lcg]            = rh0;
            *(uint4*)&b[lrow * R_ASTR + lcg + 4]        = rh1;
            *(uint4*)&b[1152 + lrow * R_ASTR + lcg]     = rl0;
            *(uint4*)&b[1152 + lrow * R_ASTR + lcg + 4] = rl1;
        }
        __syncthreads();

        for (int c = 0; c < 16; c++) {
            if (c < 15) {
                const int kb2 = (c + 1) * 32;
                rh0 = *(const uint4*)(Ah + kb2);     rh1 = *(const uint4*)(Ah + kb2 + 4);
                rl0 = *(const uint4*)(Al + kb2);     rl1 = *(const uint4*)(Al + kb2 + 4);
            }
            const uint32_t* ab = &sm[R_ABUF + (c & 1) * R_ABUFSZ];
#pragma unroll
            for (int kk = 0; kk < 4; kk++) {
                const int kb8 = kk * 8;
                uint32_t ah[4], al[4];
                ah[0] = ab[(wm + grp)     * R_ASTR + kb8 + qid];
                ah[1] = ab[(wm + grp + 8) * R_ASTR + kb8 + qid];
                ah[2] = ab[(wm + grp)     * R_ASTR + kb8 + qid + 4];
                ah[3] = ab[(wm + grp + 8) * R_ASTR + kb8 + qid + 4];
                al[0] = ab[1152 + (wm + grp)     * R_ASTR + kb8 + qid];
                al[1] = ab[1152 + (wm + grp + 8) * R_ASTR + kb8 + qid];
                al[2] = ab[1152 + (wm + grp)     * R_ASTR + kb8 + qid + 4];
                al[3] = ab[1152 + (wm + grp + 8) * R_ASTR + kb8 + qid + 4];
                const int kcol = c * 32 + kb8 + qid;
#pragma unroll
                for (int nt = 0; nt < 2; nt++) {
                    const int br = wn + nt * 8 + grp;
                    const uint32_t bh0 = sm[R_WHI + br * R_WSTR + kcol];
                    const uint32_t bh1 = sm[R_WHI + br * R_WSTR + kcol + 4];
                    const uint32_t bl0 = sm[R_WLO + br * R_WSTR + kcol];
                    const uint32_t bl1 = sm[R_WLO + br * R_WSTR + kcol + 4];
                    mma16(acc[nt], ah, bh0, bh1);
                    mma16(acc[nt], ah, bl0, bl1);
                    mma16(acc[nt], al, bh0, bh1);
                }
            }
            if (c < 15) {
                uint32_t* b = &sm[R_ABUF + ((c + 1) & 1) * R_ABUFSZ];
                *(uint4*)&b[lrow * R_ASTR + lcg]            = rh0;
                *(uint4*)&b[lrow * R_ASTR + lcg + 4]        = rh1;
                *(uint4*)&b[1152 + lrow * R_ASTR + lcg]     = rl0;
                *(uint4*)&b[1152 + lrow * R_ASTR + lcg + 4] = rl1;
            }
            __syncthreads();
        }

        // Epilogue
        const size_t tb = (size_t)t * BH_;
        const size_t pb = (size_t)t * (B_ * H2);
#pragma unroll
        for (int nt = 0; nt < 2; nt++) {
            const int col = n0 + wn + nt * 8 + 2 * qid;
            const int r0 = m0 + wm + grp;
            const float2 p0 = *(const float2*)&P[tb + (size_t)r0 * H_ + col];
            const float2 p1 = *(const float2*)&P[tb + (size_t)(r0 + 8) * H_ + col];
            const float v00 = fast_tanh(acc[nt][0] + p0.x);
            const float v01 = fast_tanh(acc[nt][1] + p0.y);
            const float v10 = fast_tanh(acc[nt][2] + p1.x);
            const float v11 = fast_tanh(acc[nt][3] + p1.y);
            uint32_t hi0, lo0, hi1, lo1;
            splitpack(v00, v01, hi0, lo0);
            splitpack(v10, v11, hi1, lo1);
            pohi[pb + (size_t)r0 * H2 + (col >> 1)] = hi0;
            polo[pb + (size_t)r0 * H2 + (col >> 1)] = lo0;
            pohi[pb + (size_t)(r0 + 8) * H2 + (col >> 1)] = hi1;
            polo[pb + (size_t)(r0 + 8) * H2 + (col >> 1)] = lo1;
            if (Yout) {
                float2 a = { v00, v01 }, b = { v10, v11 };
                *(float2*)&Yout[tb + (size_t)r0 * H_ + col] = a;
                *(float2*)&Yout[tb + (size_t)(r0 + 8) * H_ + col] = b;
            }
            if (t == T_ - 1) {
                float2 a = { v00, v01 }, b = { v10, v11 };
                *(float2*)&hn[(size_t)r0 * H_ + col] = a;
                *(float2*)&hn[(size_t)(r0 + 8) * H_ + col] = b;
            }
        }

        if (t < T_ - 1) {
            __syncthreads();
            if (tid == 0) {
                __threadfence();
                const unsigned int old = atomicAdd(&g_cnt, 1u);
                if (old == REC_CTAS - 1) {
                    atomicExch(&g_cnt, 0u);
                    __threadfence();
                    atomicAdd(&g_gen, 1u);
                } else {
                    const unsigned int target = gen0 + (unsigned int)t + 1u;
                    while (*(volatile unsigned int*)&g_gen < target) __nanosleep(32);
                }
                __threadfence();
            }
            __syncthreads();
        }
    }
}

// ---------------------------------------------------------------------------
extern "C" void kernel_launch(void* const* d_in, const int* in_sizes, int n_in,
                              void* d_out, int out_size)
{
    const float* inputs = (const float*)d_in[0];
    const float* hxs    = (const float*)d_in[1];
    const float* W_ih   = (const float*)d_in[2];
    const float* b_ih   = (const float*)d_in[3];
    const float* W_hh   = (const float*)d_in[4];
    const float* b_hh   = (const float*)d_in[5];
    float* out = (float*)d_out;

    float* P;
    uint32_t *xhi0, *xlo0, *xhi1, *xlo1, *uihi, *uilo, *whhi, *whlo, *hxhi, *hxlo;
    cudaGetSymbolAddress((void**)&P, g_P);
    cudaGetSymbolAddress((void**)&xhi0, g_xhi0);
    cudaGetSymbolAddress((void**)&xlo0, g_xlo0);
    cudaGetSymbolAddress((void**)&xhi1, g_xhi1);
    cudaGetSymbolAddress((void**)&xlo1, g_xlo1);
    cudaGetSymbolAddress((void**)&uihi, g_uihi);
    cudaGetSymbolAddress((void**)&uilo, g_uilo);
    cudaGetSymbolAddress((void**)&whhi, g_whhi);
    cudaGetSymbolAddress((void**)&whlo, g_whlo);
    cudaGetSymbolAddress((void**)&hxhi, g_hxhi);
    cudaGetSymbolAddress((void**)&hxlo, g_hxlo);

    cudaFuncSetAttribute(proj_kernel,  cudaFuncAttributeMaxDynamicSharedMemorySize, P_SMEM_BYTES);
    cudaFuncSetAttribute(recur_kernel, cudaFuncAttributeMaxDynamicSharedMemorySize, R_SMEM_BYTES);

    // One-time splits into packed bf16 hi/lo planes.
    split_w_kernel<<<LHH2 / 256, 256>>>(W_ih, W_hh);
    split_x_kernel<<<(TB_ * H2) / 256, 256>>>(inputs);
    split_hx_kernel<<<(L_ * B_ * H2) / 256, 256>>>(hxs);

    uint32_t* xin_hi[2]  = { xhi0, xhi1 };
    uint32_t* xin_lo[2]  = { xlo0, xlo1 };

    const dim3 proj_grid(H_ / 64, TB_ / 128);   // (16, 256)
    const dim3 rec_grid(H_ / 32, B_ / 32);      // (32, 4) = 128 CTAs

    for (int l = 0; l < L_; l++) {
        const int pin = l & 1, pout = pin ^ 1;
        const size_t wo = (size_t)l * H_ * H2;

        proj_kernel<<<proj_grid, 256, P_SMEM_BYTES>>>(
            xin_hi[pin], xin_lo[pin], uihi + wo, uilo + wo,
            b_ih + (size_t)l * H_, b_hh + (size_t)l * H_, P);

        recur_kernel<<<rec_grid, 128, R_SMEM_BYTES>>>(
            hxhi + (size_t)l * (B_ * H2), hxlo + (size_t)l * (B_ * H2),
            whhi + wo, whlo + wo, P,
            xin_hi[pout], xin_lo[pout],
            (l == L_ - 1) ? out : nullptr,
            out + (size_t)TBH_ + (size_t)l * BH_);
    }
}

// round 7
// speedup vs baseline: 2.9709x; 1.1007x over previous
#include <cuda_runtime.h>
#include <cuda_bf16.h>
#include <cstdint>
#include <math.h>

#define T_ 256
#define B_ 128
#define H_ 1024
#define H2 512                    /* H/2 packed u32 pairs */
#define L_ 4
#define TB_ 32768
#define BH_ 131072
#define TBH_ 33554432
#define LHH2 (L_ * H_ * H2)       /* 2097152 */

// ---------------------------------------------------------------------------
// Device globals (allocation-free scratch)
// ---------------------------------------------------------------------------
__device__ float g_P[TBH_];
__device__ uint32_t g_xhi0[TB_ * H2];
__device__ uint32_t g_xlo0[TB_ * H2];
__device__ uint32_t g_xhi1[TB_ * H2];
__device__ uint32_t g_xlo1[TB_ * H2];
__device__ uint32_t g_uihi[LHH2], g_uilo[LHH2];
__device__ uint32_t g_whhi[LHH2], g_whlo[LHH2];
__device__ uint32_t g_hxhi[L_ * B_ * H2], g_hxlo[L_ * B_ * H2];
__device__ unsigned int g_cnt4[4] = {0, 0, 0, 0};   // per-m-group barrier
__device__ unsigned int g_gen4[4] = {0, 0, 0, 0};

// ---------------------------------------------------------------------------
// Helpers
// ---------------------------------------------------------------------------
__device__ __forceinline__ uint32_t smem_u32(const void* p) {
    uint32_t a;
    asm("{ .reg .u64 t; cvta.to.shared.u64 t, %1; cvt.u32.u64 %0, t; }" : "=r"(a) : "l"(p));
    return a;
}
__device__ __forceinline__ void splitpack(float x0, float x1, uint32_t& hi, uint32_t& lo) {
    __nv_bfloat16 h0 = __float2bfloat16(x0);
    __nv_bfloat16 h1 = __float2bfloat16(x1);
    __nv_bfloat16 l0 = __float2bfloat16(x0 - __bfloat162float(h0));
    __nv_bfloat16 l1 = __float2bfloat16(x1 - __bfloat162float(h1));
    hi = (uint32_t)__bfloat16_as_ushort(h0) | ((uint32_t)__bfloat16_as_ushort(h1) << 16);
    lo = (uint32_t)__bfloat16_as_ushort(l0) | ((uint32_t)__bfloat16_as_ushort(l1) << 16);
}
__device__ __forceinline__ void mma16(float* d, const uint32_t* a, uint32_t b0, uint32_t b1) {
    asm volatile("mma.sync.aligned.m16n8k16.row.col.f32.bf16.bf16.f32 "
                 "{%0,%1,%2,%3}, {%4,%5,%6,%7}, {%8,%9}, {%0,%1,%2,%3};"
                 : "+f"(d[0]), "+f"(d[1]), "+f"(d[2]), "+f"(d[3])
                 : "r"(a[0]), "r"(a[1]), "r"(a[2]), "r"(a[3]), "r"(b0), "r"(b1));
}
#define LDSM4(r, addr) \
    asm volatile("ldmatrix.sync.aligned.m8n8.x4.shared.b16 {%0,%1,%2,%3}, [%4];" \
                 : "=r"((r)[0]), "=r"((r)[1]), "=r"((r)[2]), "=r"((r)[3]) : "r"(addr))
__device__ __forceinline__ float fast_tanh(float x) {
    const float e = __expf(2.0f * x);
    return 1.0f - __fdividef(2.0f, e + 1.0f);
}

// ---------------------------------------------------------------------------
// One-time splits
// ---------------------------------------------------------------------------
__global__ __launch_bounds__(256)
void split_w_kernel(const float* __restrict__ Wih, const float* __restrict__ Whh)
{
    const size_t i = (size_t)blockIdx.x * 256 + threadIdx.x;
    uint32_t hi, lo;
    splitpack(Wih[2 * i], Wih[2 * i + 1], hi, lo);
    g_uihi[i] = hi; g_uilo[i] = lo;
    splitpack(Whh[2 * i], Whh[2 * i + 1], hi, lo);
    g_whhi[i] = hi; g_whlo[i] = lo;
}
__global__ __launch_bounds__(256)
void split_x_kernel(const float* __restrict__ X)
{
    const size_t i = (size_t)blockIdx.x * 256 + threadIdx.x;
    uint32_t hi, lo;
    splitpack(X[2 * i], X[2 * i + 1], hi, lo);
    g_xhi0[i] = hi; g_xlo0[i] = lo;
}
__global__ __launch_bounds__(256)
void split_hx_kernel(const float* __restrict__ hx)
{
    const size_t i = (size_t)blockIdx.x * 256 + threadIdx.x;
    uint32_t hi, lo;
    splitpack(hx[2 * i], hx[2 * i + 1], hi, lo);
    g_hxhi[i] = hi; g_hxlo[i] = lo;
}

// ---------------------------------------------------------------------------
// Input projection: P = X @ W^T + bi + bh.  M=32768, N=1024, K=1024.
// CTA 128x64, BK=32 elems (16 u32), 256 thr (8 warps: 4m x 2n), warp m32 n32.
// Fragments via ldmatrix.x4.
// ---------------------------------------------------------------------------
#define P_STR 20
#define P_SAHI 0
#define P_SALO 2560
#define P_SBHI 5120
#define P_SBLO 6400
#define P_SMEM_BYTES (7680u * 4u)

__global__ __launch_bounds__(256, 2)
void proj_kernel(const uint32_t* __restrict__ Xhi, const uint32_t* __restrict__ Xlo,
                 const uint32_t* __restrict__ Whi_, const uint32_t* __restrict__ Wlo_,
                 const float* __restrict__ bi, const float* __restrict__ bhh,
                 float* __restrict__ P)
{
    extern __shared__ uint32_t sm[];
    const uint32_t smb = smem_u32(sm);
    const int tid = threadIdx.x, wid = tid >> 5, lane = tid & 31;
    const int grp = lane >> 2, qid = lane & 3;
    const int m0 = blockIdx.y * 128, n0 = blockIdx.x * 64;
    const int wm = (wid >> 1) * 32, wn = (wid & 1) * 32;

    // ldmatrix lane-address offsets (u32 units)
    const int arow_f = (lane & 7) + ((lane >> 3) & 1) * 8;    // row within m16
    const uint32_t akh = (lane >> 4) * 4;                     // k-half
    const uint32_t aoff0 = (uint32_t)(wm + arow_f) * P_STR + akh;
    const uint32_t aoff1 = (uint32_t)(wm + 16 + arow_f) * P_STR + akh;
    const int mB = lane >> 3;
    const int brow_f = (mB >> 1) * 8 + (lane & 7);
    const uint32_t bkh = (uint32_t)(mB & 1) * 4;
    const uint32_t boff0 = (uint32_t)(wn + brow_f) * P_STR + bkh;        // nt0,nt1
    const uint32_t boff1 = (uint32_t)(wn + 16 + brow_f) * P_STR + bkh;   // nt2,nt3

    const int arow = tid >> 1, acg = (tid & 1) * 8;
    const int brow = tid >> 2, bcg = (tid & 3) * 4;

    const uint32_t* Ah = Xhi  + (size_t)(m0 + arow) * H2 + acg;
    const uint32_t* Al = Xlo  + (size_t)(m0 + arow) * H2 + acg;
    const uint32_t* Bh = Whi_ + (size_t)(n0 + brow) * H2 + bcg;
    const uint32_t* Bl = Wlo_ + (size_t)(n0 + brow) * H2 + bcg;

    float acc[2][4][4];
#pragma unroll
    for (int mt = 0; mt < 2; mt++)
#pragma unroll
        for (int nt = 0; nt < 4; nt++)
#pragma unroll
            for (int i = 0; i < 4; i++) acc[mt][nt][i] = 0.0f;

    uint4 rah0 = *(const uint4*)Ah, rah1 = *(const uint4*)(Ah + 4);
    uint4 ral0 = *(const uint4*)Al, ral1 = *(const uint4*)(Al + 4);
    uint4 rbh  = *(const uint4*)Bh, rbl  = *(const uint4*)Bl;

    for (int kb2 = 0; kb2 < H2; kb2 += 16) {
        __syncthreads();
        *(uint4*)&sm[P_SAHI + arow * P_STR + acg]     = rah0;
        *(uint4*)&sm[P_SAHI + arow * P_STR + acg + 4] = rah1;
        *(uint4*)&sm[P_SALO + arow * P_STR + acg]     = ral0;
        *(uint4*)&sm[P_SALO + arow * P_STR + acg + 4] = ral1;
        *(uint4*)&sm[P_SBHI + brow * P_STR + bcg]     = rbh;
        *(uint4*)&sm[P_SBLO + brow * P_STR + bcg]     = rbl;
        __syncthreads();
        if (kb2 + 16 < H2) {
            rah0 = *(const uint4*)(Ah + kb2 + 16); rah1 = *(const uint4*)(Ah + kb2 + 20);
            ral0 = *(const uint4*)(Al + kb2 + 16); ral1 = *(const uint4*)(Al + kb2 + 20);
            rbh  = *(const uint4*)(Bh + kb2 + 16); rbl  = *(const uint4*)(Bl + kb2 + 16);
        }
#pragma unroll
        for (int kk = 0; kk < 2; kk++) {
            const uint32_t kb8 = kk * 8;
            uint32_t ah0[4], ah1[4], al0[4], al1[4];
            uint32_t bh01[4], bh23[4], bl01[4], bl23[4];
            LDSM4(ah0, smb + 4 * (P_SAHI + aoff0 + kb8));
            LDSM4(ah1, smb + 4 * (P_SAHI + aoff1 + kb8));
            LDSM4(al0, smb + 4 * (P_SALO + aoff0 + kb8));
            LDSM4(al1, smb + 4 * (P_SALO + aoff1 + kb8));
            LDSM4(bh01, smb + 4 * (P_SBHI + boff0 + kb8));
            LDSM4(bh23, smb + 4 * (P_SBHI + boff1 + kb8));
            LDSM4(bl01, smb + 4 * (P_SBLO + boff0 + kb8));
            LDSM4(bl23, smb + 4 * (P_SBLO + boff1 + kb8));
#pragma unroll
            for (int nt = 0; nt < 4; nt++) {
                const uint32_t* bhp = (nt < 2) ? bh01 : bh23;
                const uint32_t* blp = (nt < 2) ? bl01 : bl23;
                const int o = (nt & 1) * 2;
                mma16(acc[0][nt], ah0, bhp[o], bhp[o + 1]);
                mma16(acc[1][nt], ah1, bhp[o], bhp[o + 1]);
                mma16(acc[0][nt], ah0, blp[o], blp[o + 1]);
                mma16(acc[1][nt], ah1, blp[o], blp[o + 1]);
                mma16(acc[0][nt], al0, bhp[o], bhp[o + 1]);
                mma16(acc[1][nt], al1, bhp[o], bhp[o + 1]);
            }
        }
    }

#pragma unroll
    for (int mt = 0; mt < 2; mt++) {
#pragma unroll
        for (int nt = 0; nt < 4; nt++) {
            const int col = n0 + wn + nt * 8 + 2 * qid;
            const float bx = bi[col] + bhh[col];
            const float by = bi[col + 1] + bhh[col + 1];
            const int r0 = m0 + wm + mt * 16 + grp;
            float2 v0 = { acc[mt][nt][0] + bx, acc[mt][nt][1] + by };
            float2 v1 = { acc[mt][nt][2] + bx, acc[mt][nt][3] + by };
            *(float2*)&P[(size_t)r0 * H_ + col] = v0;
            *(float2*)&P[(size_t)(r0 + 8) * H_ + col] = v1;
        }
    }
}

// ---------------------------------------------------------------------------
// Persistent recurrence. Grid (32 n-tiles, 4 m-groups) = 128 CTAs, 128 thr
// (4 warps: 2m x 2n, warp m16 n16). W stripe resident in smem; A double-
// buffered; fragments via ldmatrix; 6 independent accumulator chains;
// per-m-group barrier (32 CTAs each).
// ---------------------------------------------------------------------------
#define R_WSTR 516
#define R_ASTR 36
#define R_WHI 0
#define R_WLO 16512
#define R_ABUF 33024
#define R_ABUFSZ 2304
#define R_SMEM_BYTES ((33024u + 4608u) * 4u)

__global__ __launch_bounds__(128, 1)
void recur_kernel(const uint32_t* __restrict__ hxhi, const uint32_t* __restrict__ hxlo,
                  const uint32_t* __restrict__ Whi_, const uint32_t* __restrict__ Wlo_,
                  const float* __restrict__ P,
                  uint32_t* __restrict__ pohi, uint32_t* __restrict__ polo,
                  float* __restrict__ Yout,
                  float* __restrict__ hn)
{
    extern __shared__ uint32_t sm[];
    const uint32_t smb = smem_u32(sm);
    __shared__ unsigned int s_gen;

    const int tid = threadIdx.x, wid = tid >> 5, lane = tid & 31;
    const int grp = lane >> 2, qid = lane & 3;
    const int n0 = blockIdx.x * 32, mg = blockIdx.y, m0 = mg * 32;
    const int wm = (wid >> 1) * 16, wn = (wid & 1) * 16;

    // ldmatrix lane offsets
    const uint32_t aoff = (uint32_t)(wm + (lane & 7) + ((lane >> 3) & 1) * 8) * R_ASTR
                        + (lane >> 4) * 4;
    const int mB = lane >> 3;
    const uint32_t boff = (uint32_t)(wn + (mB >> 1) * 8 + (lane & 7)) * R_WSTR
                        + (uint32_t)(mB & 1) * 4;

    // Stage W stripe (32 rows x 512 u32 per plane).
    for (int idx = tid * 4; idx < 32 * H2; idx += 128 * 4) {
        const int r = idx >> 9, c = idx & (H2 - 1);
        *(uint4*)&sm[R_WHI + r * R_WSTR + c] = *(const uint4*)&Whi_[(size_t)(n0 + r) * H2 + c];
        *(uint4*)&sm[R_WLO + r * R_WSTR + c] = *(const uint4*)&Wlo_[(size_t)(n0 + r) * H2 + c];
    }
    if (tid == 0) s_gen = *(volatile unsigned int*)&g_gen4[mg];
    __syncthreads();
    const unsigned int gen0 = s_gen;

    const int lrow = tid >> 2, lcg = (tid & 3) * 8;

    for (int t = 0; t < T_; t++) {
        const uint32_t* Ahp = t ? (pohi + (size_t)(t - 1) * (B_ * H2)) : hxhi;
        const uint32_t* Alp = t ? (polo + (size_t)(t - 1) * (B_ * H2)) : hxlo;
        const uint32_t* Ah = Ahp + (size_t)(m0 + lrow) * H2 + lcg;
        const uint32_t* Al = Alp + (size_t)(m0 + lrow) * H2 + lcg;

        float a00[4] = {0,0,0,0}, a01[4] = {0,0,0,0}, a02[4] = {0,0,0,0};
        float a10[4] = {0,0,0,0}, a11[4] = {0,0,0,0}, a12[4] = {0,0,0,0};

        uint4 rh0 = *(const uint4*)Ah, rh1 = *(const uint4*)(Ah + 4);
        uint4 rl0 = *(const uint4*)Al, rl1 = *(const uint4*)(Al + 4);
        {
            uint32_t* b = &sm[R_ABUF];
            *(uint4*)&b[lrow * R_ASTR + lcg]            = rh0;
            *(uint4*)&b[lrow * R_ASTR + lcg + 4]        = rh1;
            *(uint4*)&b[1152 + lrow * R_ASTR + lcg]     = rl0;
            *(uint4*)&b[1152 + lrow * R_ASTR + lcg + 4] = rl1;
        }
        __syncthreads();

        for (int c = 0; c < 16; c++) {
            if (c < 15) {
                const int kb2 = (c + 1) * 32;
                rh0 = *(const uint4*)(Ah + kb2); rh1 = *(const uint4*)(Ah + kb2 + 4);
                rl0 = *(const uint4*)(Al + kb2); rl1 = *(const uint4*)(Al + kb2 + 4);
            }
            const uint32_t abase = smb + 4 * (R_ABUF + (c & 1) * R_ABUFSZ + aoff);
            const uint32_t kcb = c * 32;
#pragma unroll
            for (int kk = 0; kk < 4; kk++) {
                const uint32_t kb8 = kk * 8;
                uint32_t ah[4], al[4], bh[4], bl[4];
                LDSM4(ah, abase + 4 * kb8);
                LDSM4(al, abase + 4 * (1152 + kb8));
                LDSM4(bh, smb + 4 * (R_WHI + boff + kcb + kb8));
                LDSM4(bl, smb + 4 * (R_WLO + boff + kcb + kb8));
                mma16(a00, ah, bh[0], bh[1]);
                mma16(a10, ah, bh[2], bh[3]);
                mma16(a01, ah, bl[0], bl[1]);
                mma16(a11, ah, bl[2], bl[3]);
                mma16(a02, al, bh[0], bh[1]);
                mma16(a12, al, bh[2], bh[3]);
            }
            if (c < 15) {
                uint32_t* b = &sm[R_ABUF + ((c + 1) & 1) * R_ABUFSZ];
                *(uint4*)&b[lrow * R_ASTR + lcg]            = rh0;
                *(uint4*)&b[lrow * R_ASTR + lcg + 4]        = rh1;
                *(uint4*)&b[1152 + lrow * R_ASTR + lcg]     = rl0;
                *(uint4*)&b[1152 + lrow * R_ASTR + lcg + 4] = rl1;
            }
            __syncthreads();
        }

        // Epilogue
        const size_t tb = (size_t)t * BH_;
        const size_t pb = (size_t)t * (B_ * H2);
#pragma unroll
        for (int nt = 0; nt < 2; nt++) {
            float ac[4];
            if (nt == 0) {
#pragma unroll
                for (int i = 0; i < 4; i++) ac[i] = a00[i] + a01[i] + a02[i];
            } else {
#pragma unroll
                for (int i = 0; i < 4; i++) ac[i] = a10[i] + a11[i] + a12[i];
            }
            const int col = n0 + wn + nt * 8 + 2 * qid;
            const int r0 = m0 + wm + grp;
            const float2 p0 = *(const float2*)&P[tb + (size_t)r0 * H_ + col];
            const float2 p1 = *(const float2*)&P[tb + (size_t)(r0 + 8) * H_ + col];
            const float v00 = fast_tanh(ac[0] + p0.x);
            const float v01 = fast_tanh(ac[1] + p0.y);
            const float v10 = fast_tanh(ac[2] + p1.x);
            const float v11 = fast_tanh(ac[3] + p1.y);
            uint32_t hi0, lo0, hi1, lo1;
            splitpack(v00, v01, hi0, lo0);
            splitpack(v10, v11, hi1, lo1);
            pohi[pb + (size_t)r0 * H2 + (col >> 1)] = hi0;
            polo[pb + (size_t)r0 * H2 + (col >> 1)] = lo0;
            pohi[pb + (size_t)(r0 + 8) * H2 + (col >> 1)] = hi1;
            polo[pb + (size_t)(r0 + 8) * H2 + (col >> 1)] = lo1;
            if (Yout) {
                float2 a = { v00, v01 }, b = { v10, v11 };
                *(float2*)&Yout[tb + (size_t)r0 * H_ + col] = a;
                *(float2*)&Yout[tb + (size_t)(r0 + 8) * H_ + col] = b;
            }
            if (t == T_ - 1) {
                float2 a = { v00, v01 }, b = { v10, v11 };
                *(float2*)&hn[(size_t)r0 * H_ + col] = a;
                *(float2*)&hn[(size_t)(r0 + 8) * H_ + col] = b;
            }
        }

        // Per-m-group barrier: only the 32 CTAs sharing this m-group must sync.
        if (t < T_ - 1) {
            __syncthreads();
            if (tid == 0) {
                __threadfence();
                const unsigned int old = atomicAdd(&g_cnt4[mg], 1u);
                if (old == 31u) {
                    atomicExch(&g_cnt4[mg], 0u);
                    __threadfence();
                    atomicAdd(&g_gen4[mg], 1u);
                } else {
                    const unsigned int target = gen0 + (unsigned int)t + 1u;
                    while (*(volatile unsigned int*)&g_gen4[mg] < target) __nanosleep(32);
                }
                __threadfence();
            }
            __syncthreads();
        }
    }
}

// ---------------------------------------------------------------------------
extern "C" void kernel_launch(void* const* d_in, const int* in_sizes, int n_in,
                              void* d_out, int out_size)
{
    const float* inputs = (const float*)d_in[0];
    const float* hxs    = (const float*)d_in[1];
    const float* W_ih   = (const float*)d_in[2];
    const float* b_ih   = (const float*)d_in[3];
    const float* W_hh   = (const float*)d_in[4];
    const float* b_hh   = (const float*)d_in[5];
    float* out = (float*)d_out;

    float* P;
    uint32_t *xhi0, *xlo0, *xhi1, *xlo1, *uihi, *uilo, *whhi, *whlo, *hxhi, *hxlo;
    cudaGetSymbolAddress((void**)&P, g_P);
    cudaGetSymbolAddress((void**)&xhi0, g_xhi0);
    cudaGetSymbolAddress((void**)&xlo0, g_xlo0);
    cudaGetSymbolAddress((void**)&xhi1, g_xhi1);
    cudaGetSymbolAddress((void**)&xlo1, g_xlo1);
    cudaGetSymbolAddress((void**)&uihi, g_uihi);
    cudaGetSymbolAddress((void**)&uilo, g_uilo);
    cudaGetSymbolAddress((void**)&whhi, g_whhi);
    cudaGetSymbolAddress((void**)&whlo, g_whlo);
    cudaGetSymbolAddress((void**)&hxhi, g_hxhi);
    cudaGetSymbolAddress((void**)&hxlo, g_hxlo);

    cudaFuncSetAttribute(proj_kernel,  cudaFuncAttributeMaxDynamicSharedMemorySize, P_SMEM_BYTES);
    cudaFuncSetAttribute(recur_kernel, cudaFuncAttributeMaxDynamicSharedMemorySize, R_SMEM_BYTES);

    split_w_kernel<<<LHH2 / 256, 256>>>(W_ih, W_hh);
    split_x_kernel<<<(TB_ * H2) / 256, 256>>>(inputs);
    split_hx_kernel<<<(L_ * B_ * H2) / 256, 256>>>(hxs);

    uint32_t* xin_hi[2] = { xhi0, xhi1 };
    uint32_t* xin_lo[2] = { xlo0, xlo1 };

    const dim3 proj_grid(H_ / 64, TB_ / 128);   // (16, 256)
    const dim3 rec_grid(H_ / 32, B_ / 32);      // (32, 4) = 128 CTAs

    for (int l = 0; l < L_; l++) {
        const int pin = l & 1, pout = pin ^ 1;
        const size_t wo = (size_t)l * H_ * H2;

        proj_kernel<<<proj_grid, 256, P_SMEM_BYTES>>>(
            xin_hi[pin], xin_lo[pin], uihi + wo, uilo + wo,
            b_ih + (size_t)l * H_, b_hh + (size_t)l * H_, P);

        recur_kernel<<<rec_grid, 128, R_SMEM_BYTES>>>(
            hxhi + (size_t)l * (B_ * H2), hxlo + (size_t)l * (B_ * H2),
            whhi + wo, whlo + wo, P,
            xin_hi[pout], xin_lo[pout],
            (l == L_ - 1) ? out : nullptr,
            out + (size_t)TBH_ + (size_t)l * BH_);
    }
}

// round 8
// speedup vs baseline: 3.7277x; 1.2547x over previous
#include <cuda_runtime.h>
#include <cuda_bf16.h>
#include <cstdint>
#include <math.h>

#define T_ 256
#define B_ 128
#define H_ 1024
#define H2 512                    /* H/2 packed u32 pairs */
#define L_ 4
#define TB_ 32768
#define BH_ 131072
#define TBH_ 33554432
#define LHH2 (L_ * H_ * H2)       /* 2097152 */

// ---------------------------------------------------------------------------
// Device globals (allocation-free scratch)
// ---------------------------------------------------------------------------
__device__ float g_P[TBH_];
__device__ uint32_t g_xhi0[TB_ * H2];
__device__ uint32_t g_xlo0[TB_ * H2];
__device__ uint32_t g_xhi1[TB_ * H2];
__device__ uint32_t g_xlo1[TB_ * H2];
__device__ uint32_t g_uihi[LHH2], g_uilo[LHH2];
__device__ uint32_t g_whhi[LHH2], g_whlo[LHH2];
__device__ uint32_t g_hxhi[L_ * B_ * H2], g_hxlo[L_ * B_ * H2];
__device__ unsigned int g_cnt4[4] = {0, 0, 0, 0};   // per-m-group barrier
__device__ unsigned int g_gen4[4] = {0, 0, 0, 0};

// ---------------------------------------------------------------------------
// Helpers
// ---------------------------------------------------------------------------
__device__ __forceinline__ uint32_t smem_u32(const void* p) {
    uint32_t a;
    asm("{ .reg .u64 t; cvta.to.shared.u64 t, %1; cvt.u32.u64 %0, t; }" : "=r"(a) : "l"(p));
    return a;
}
__device__ __forceinline__ void splitpack(float x0, float x1, uint32_t& hi, uint32_t& lo) {
    __nv_bfloat16 h0 = __float2bfloat16(x0);
    __nv_bfloat16 h1 = __float2bfloat16(x1);
    __nv_bfloat16 l0 = __float2bfloat16(x0 - __bfloat162float(h0));
    __nv_bfloat16 l1 = __float2bfloat16(x1 - __bfloat162float(h1));
    hi = (uint32_t)__bfloat16_as_ushort(h0) | ((uint32_t)__bfloat16_as_ushort(h1) << 16);
    lo = (uint32_t)__bfloat16_as_ushort(l0) | ((uint32_t)__bfloat16_as_ushort(l1) << 16);
}
__device__ __forceinline__ void mma16(float* d, const uint32_t* a, uint32_t b0, uint32_t b1) {
    asm volatile("mma.sync.aligned.m16n8k16.row.col.f32.bf16.bf16.f32 "
                 "{%0,%1,%2,%3}, {%4,%5,%6,%7}, {%8,%9}, {%0,%1,%2,%3};"
                 : "+f"(d[0]), "+f"(d[1]), "+f"(d[2]), "+f"(d[3])
                 : "r"(a[0]), "r"(a[1]), "r"(a[2]), "r"(a[3]), "r"(b0), "r"(b1));
}
#define LDSM4(r, addr) \
    asm volatile("ldmatrix.sync.aligned.m8n8.x4.shared.b16 {%0,%1,%2,%3}, [%4];" \
                 : "=r"((r)[0]), "=r"((r)[1]), "=r"((r)[2]), "=r"((r)[3]) : "r"(addr))
__device__ __forceinline__ float fast_tanh(float x) {
    const float e = __expf(2.0f * x);
    return 1.0f - __fdividef(2.0f, e + 1.0f);
}

// ---------------------------------------------------------------------------
// One-time splits
// ---------------------------------------------------------------------------
__global__ __launch_bounds__(256)
void split_w_kernel(const float* __restrict__ Wih, const float* __restrict__ Whh)
{
    const size_t i = (size_t)blockIdx.x * 256 + threadIdx.x;
    uint32_t hi, lo;
    splitpack(Wih[2 * i], Wih[2 * i + 1], hi, lo);
    g_uihi[i] = hi; g_uilo[i] = lo;
    splitpack(Whh[2 * i], Whh[2 * i + 1], hi, lo);
    g_whhi[i] = hi; g_whlo[i] = lo;
}
__global__ __launch_bounds__(256)
void split_x_kernel(const float* __restrict__ X)
{
    const size_t i = (size_t)blockIdx.x * 256 + threadIdx.x;
    uint32_t hi, lo;
    splitpack(X[2 * i], X[2 * i + 1], hi, lo);
    g_xhi0[i] = hi; g_xlo0[i] = lo;
}
__global__ __launch_bounds__(256)
void split_hx_kernel(const float* __restrict__ hx)
{
    const size_t i = (size_t)blockIdx.x * 256 + threadIdx.x;
    uint32_t hi, lo;
    splitpack(hx[2 * i], hx[2 * i + 1], hi, lo);
    g_hxhi[i] = hi; g_hxlo[i] = lo;
}

// ---------------------------------------------------------------------------
// Input projection: P = X @ W^T + bi + bh.  M=32768, N=1024, K=1024.
// CTA 128x64, BK=32 elems (16 u32), 256 thr (8 warps: 4m x 2n), warp m32 n32.
// ---------------------------------------------------------------------------
#define P_STR 20
#define P_SAHI 0
#define P_SALO 2560
#define P_SBHI 5120
#define P_SBLO 6400
#define P_SMEM_BYTES (7680u * 4u)

__global__ __launch_bounds__(256, 2)
void proj_kernel(const uint32_t* __restrict__ Xhi, const uint32_t* __restrict__ Xlo,
                 const uint32_t* __restrict__ Whi_, const uint32_t* __restrict__ Wlo_,
                 const float* __restrict__ bi, const float* __restrict__ bhh,
                 float* __restrict__ P)
{
    extern __shared__ uint32_t sm[];
    const uint32_t smb = smem_u32(sm);
    const int tid = threadIdx.x, wid = tid >> 5, lane = tid & 31;
    const int grp = lane >> 2, qid = lane & 3;
    const int m0 = blockIdx.y * 128, n0 = blockIdx.x * 64;
    const int wm = (wid >> 1) * 32, wn = (wid & 1) * 32;

    const int arow_f = (lane & 7) + ((lane >> 3) & 1) * 8;
    const uint32_t akh = (lane >> 4) * 4;
    const uint32_t aoff0 = (uint32_t)(wm + arow_f) * P_STR + akh;
    const uint32_t aoff1 = (uint32_t)(wm + 16 + arow_f) * P_STR + akh;
    const int mB = lane >> 3;
    const int brow_f = (mB >> 1) * 8 + (lane & 7);
    const uint32_t bkh = (uint32_t)(mB & 1) * 4;
    const uint32_t boff0 = (uint32_t)(wn + brow_f) * P_STR + bkh;
    const uint32_t boff1 = (uint32_t)(wn + 16 + brow_f) * P_STR + bkh;

    const int arow = tid >> 1, acg = (tid & 1) * 8;
    const int brow = tid >> 2, bcg = (tid & 3) * 4;

    const uint32_t* Ah = Xhi  + (size_t)(m0 + arow) * H2 + acg;
    const uint32_t* Al = Xlo  + (size_t)(m0 + arow) * H2 + acg;
    const uint32_t* Bh = Whi_ + (size_t)(n0 + brow) * H2 + bcg;
    const uint32_t* Bl = Wlo_ + (size_t)(n0 + brow) * H2 + bcg;

    float acc[2][4][4];
#pragma unroll
    for (int mt = 0; mt < 2; mt++)
#pragma unroll
        for (int nt = 0; nt < 4; nt++)
#pragma unroll
            for (int i = 0; i < 4; i++) acc[mt][nt][i] = 0.0f;

    uint4 rah0 = *(const uint4*)Ah, rah1 = *(const uint4*)(Ah + 4);
    uint4 ral0 = *(const uint4*)Al, ral1 = *(const uint4*)(Al + 4);
    uint4 rbh  = *(const uint4*)Bh, rbl  = *(const uint4*)Bl;

    for (int kb2 = 0; kb2 < H2; kb2 += 16) {
        __syncthreads();
        *(uint4*)&sm[P_SAHI + arow * P_STR + acg]     = rah0;
        *(uint4*)&sm[P_SAHI + arow * P_STR + acg + 4] = rah1;
        *(uint4*)&sm[P_SALO + arow * P_STR + acg]     = ral0;
        *(uint4*)&sm[P_SALO + arow * P_STR + acg + 4] = ral1;
        *(uint4*)&sm[P_SBHI + brow * P_STR + bcg]     = rbh;
        *(uint4*)&sm[P_SBLO + brow * P_STR + bcg]     = rbl;
        __syncthreads();
        if (kb2 + 16 < H2) {
            rah0 = *(const uint4*)(Ah + kb2 + 16); rah1 = *(const uint4*)(Ah + kb2 + 20);
            ral0 = *(const uint4*)(Al + kb2 + 16); ral1 = *(const uint4*)(Al + kb2 + 20);
            rbh  = *(const uint4*)(Bh + kb2 + 16); rbl  = *(const uint4*)(Bl + kb2 + 16);
        }
#pragma unroll
        for (int kk = 0; kk < 2; kk++) {
            const uint32_t kb8 = kk * 8;
            uint32_t ah0[4], ah1[4], al0[4], al1[4];
            uint32_t bh01[4], bh23[4], bl01[4], bl23[4];
            LDSM4(ah0, smb + 4 * (P_SAHI + aoff0 + kb8));
            LDSM4(ah1, smb + 4 * (P_SAHI + aoff1 + kb8));
            LDSM4(al0, smb + 4 * (P_SALO + aoff0 + kb8));
            LDSM4(al1, smb + 4 * (P_SALO + aoff1 + kb8));
            LDSM4(bh01, smb + 4 * (P_SBHI + boff0 + kb8));
            LDSM4(bh23, smb + 4 * (P_SBHI + boff1 + kb8));
            LDSM4(bl01, smb + 4 * (P_SBLO + boff0 + kb8));
            LDSM4(bl23, smb + 4 * (P_SBLO + boff1 + kb8));
#pragma unroll
            for (int nt = 0; nt < 4; nt++) {
                const uint32_t* bhp = (nt < 2) ? bh01 : bh23;
                const uint32_t* blp = (nt < 2) ? bl01 : bl23;
                const int o = (nt & 1) * 2;
                mma16(acc[0][nt], ah0, bhp[o], bhp[o + 1]);
                mma16(acc[1][nt], ah1, bhp[o], bhp[o + 1]);
                mma16(acc[0][nt], ah0, blp[o], blp[o + 1]);
                mma16(acc[1][nt], ah1, blp[o], blp[o + 1]);
                mma16(acc[0][nt], al0, bhp[o], bhp[o + 1]);
                mma16(acc[1][nt], al1, bhp[o], bhp[o + 1]);
            }
        }
    }

#pragma unroll
    for (int mt = 0; mt < 2; mt++) {
#pragma unroll
        for (int nt = 0; nt < 4; nt++) {
            const int col = n0 + wn + nt * 8 + 2 * qid;
            const float bx = bi[col] + bhh[col];
            const float by = bi[col + 1] + bhh[col + 1];
            const int r0 = m0 + wm + mt * 16 + grp;
            float2 v0 = { acc[mt][nt][0] + bx, acc[mt][nt][1] + by };
            float2 v1 = { acc[mt][nt][2] + bx, acc[mt][nt][3] + by };
            *(float2*)&P[(size_t)r0 * H_ + col] = v0;
            *(float2*)&P[(size_t)(r0 + 8) * H_ + col] = v1;
        }
    }
}

// ---------------------------------------------------------------------------
// Persistent recurrence, K-split across two warp groups.
// Grid (32 n-tiles, 4 m-groups) = 128 CTAs, 256 thr (8 warps).
// Group g (warps 4g..4g+3) computes the K-half [g*512, (g+1)*512) against the
// shared smem-resident W stripe; group 1 partial sums reduced via smem.
// 2 warps/SMSP -> tensor-pipe latency hiding.
// ---------------------------------------------------------------------------
#define R_WSTR 516
#define R_ASTR 36
#define R_WHI 0
#define R_WLO 16512
#define R_ABUF 33024
#define R_ABUFSZ 2304            /* per buffer: hi 1152 + lo 1152 */
#define R_RED (R_ABUF + 4 * R_ABUFSZ)       /* 42240 */
#define R_SMEM_U32 (R_RED + 1024)
#define R_SMEM_BYTES (R_SMEM_U32 * 4u)      /* 173056 */

__global__ __launch_bounds__(256, 1)
void recur_kernel(const uint32_t* __restrict__ hxhi, const uint32_t* __restrict__ hxlo,
                  const uint32_t* __restrict__ Whi_, const uint32_t* __restrict__ Wlo_,
                  const float* __restrict__ P,
                  uint32_t* __restrict__ pohi, uint32_t* __restrict__ polo,
                  float* __restrict__ Yout,
                  float* __restrict__ hn)
{
    extern __shared__ uint32_t sm[];
    const uint32_t smb = smem_u32(sm);
    __shared__ unsigned int s_gen;

    const int tid = threadIdx.x, wid = tid >> 5, lane = tid & 31;
    const int grp = lane >> 2, qid = lane & 3;
    const int n0 = blockIdx.x * 32, mg = blockIdx.y, m0 = mg * 32;
    const int g = wid >> 2;                  // K-half group 0/1
    const int wq = wid & 3;                  // warp within group
    const int wm = (wq >> 1) * 16, wn = (wq & 1) * 16;
    const int gbase = g * 256;               // u32 K-offset of this group's half

    // ldmatrix lane offsets
    const uint32_t aoff = (uint32_t)(wm + (lane & 7) + ((lane >> 3) & 1) * 8) * R_ASTR
                        + (lane >> 4) * 4;
    const int mB = lane >> 3;
    const uint32_t boff = (uint32_t)(wn + (mB >> 1) * 8 + (lane & 7)) * R_WSTR
                        + (uint32_t)(mB & 1) * 4;

    // Stage W stripe (32 rows x 512 u32 per plane), all 256 threads.
    for (int idx = tid * 4; idx < 32 * H2; idx += 256 * 4) {
        const int r = idx >> 9, c = idx & (H2 - 1);
        *(uint4*)&sm[R_WHI + r * R_WSTR + c] = *(const uint4*)&Whi_[(size_t)(n0 + r) * H2 + c];
        *(uint4*)&sm[R_WLO + r * R_WSTR + c] = *(const uint4*)&Wlo_[(size_t)(n0 + r) * H2 + c];
    }
    if (tid == 0) s_gen = *(volatile unsigned int*)&g_gen4[mg];
    __syncthreads();
    const unsigned int gen0 = s_gen;

    // Per-group A loader: 128 threads load one 32-u32-wide chunk per plane.
    const int ltid = tid & 127;
    const int lrow = ltid >> 2, lcg = (ltid & 3) * 8;

    for (int t = 0; t < T_; t++) {
        const uint32_t* Ahp = t ? (pohi + (size_t)(t - 1) * (B_ * H2)) : hxhi;
        const uint32_t* Alp = t ? (polo + (size_t)(t - 1) * (B_ * H2)) : hxlo;
        const uint32_t* Ah = Ahp + (size_t)(m0 + lrow) * H2 + gbase + lcg;
        const uint32_t* Al = Alp + (size_t)(m0 + lrow) * H2 + gbase + lcg;

        // Prefetch P tile (group 0 only) — hidden behind the whole k-loop.
        float2 pre[2][2];
        if (g == 0) {
#pragma unroll
            for (int nt = 0; nt < 2; nt++) {
                const int col = n0 + wn + nt * 8 + 2 * qid;
                const int r0 = m0 + wm + grp;
                pre[nt][0] = *(const float2*)&P[(size_t)t * BH_ + (size_t)r0 * H_ + col];
                pre[nt][1] = *(const float2*)&P[(size_t)t * BH_ + (size_t)(r0 + 8) * H_ + col];
            }
        }

        float a00[4] = {0,0,0,0}, a01[4] = {0,0,0,0}, a02[4] = {0,0,0,0};
        float a10[4] = {0,0,0,0}, a11[4] = {0,0,0,0}, a12[4] = {0,0,0,0};

        uint4 rh0 = *(const uint4*)Ah, rh1 = *(const uint4*)(Ah + 4);
        uint4 rl0 = *(const uint4*)Al, rl1 = *(const uint4*)(Al + 4);
        {
            uint32_t* b = &sm[R_ABUF + (g * 2) * R_ABUFSZ];
            *(uint4*)&b[lrow * R_ASTR + lcg]            = rh0;
            *(uint4*)&b[lrow * R_ASTR + lcg + 4]        = rh1;
            *(uint4*)&b[1152 + lrow * R_ASTR + lcg]     = rl0;
            *(uint4*)&b[1152 + lrow * R_ASTR + lcg + 4] = rl1;
        }
        __syncthreads();

#pragma unroll 1
        for (int c = 0; c < 8; c++) {
            if (c < 7) {
                const int kb2 = (c + 1) * 32;
                rh0 = *(const uint4*)(Ah + kb2); rh1 = *(const uint4*)(Ah + kb2 + 4);
                rl0 = *(const uint4*)(Al + kb2); rl1 = *(const uint4*)(Al + kb2 + 4);
            }
            const uint32_t abase = smb + 4 * (R_ABUF + (g * 2 + (c & 1)) * R_ABUFSZ + aoff);
            const uint32_t kcb = gbase + c * 32;
#pragma unroll
            for (int kk = 0; kk < 4; kk++) {
                const uint32_t kb8 = kk * 8;
                uint32_t ah[4], al[4], bh[4], bl[4];
                LDSM4(ah, abase + 4 * kb8);
                LDSM4(al, abase + 4 * (1152 + kb8));
                LDSM4(bh, smb + 4 * (R_WHI + boff + kcb + kb8));
                LDSM4(bl, smb + 4 * (R_WLO + boff + kcb + kb8));
                mma16(a00, ah, bh[0], bh[1]);
                mma16(a10, ah, bh[2], bh[3]);
                mma16(a01, ah, bl[0], bl[1]);
                mma16(a11, ah, bl[2], bl[3]);
                mma16(a02, al, bh[0], bh[1]);
                mma16(a12, al, bh[2], bh[3]);
            }
            if (c < 7) {
                uint32_t* b = &sm[R_ABUF + (g * 2 + ((c + 1) & 1)) * R_ABUFSZ];
                *(uint4*)&b[lrow * R_ASTR + lcg]            = rh0;
                *(uint4*)&b[lrow * R_ASTR + lcg + 4]        = rh1;
                *(uint4*)&b[1152 + lrow * R_ASTR + lcg]     = rl0;
                *(uint4*)&b[1152 + lrow * R_ASTR + lcg + 4] = rl1;
            }
            __syncthreads();
        }

        // Group 1: publish partial sums (summed across decomposition terms).
        if (g == 1) {
            float* red = (float*)&sm[R_RED];
            const int base = (wq * 32 + lane) * 8;
#pragma unroll
            for (int i = 0; i < 4; i++) {
                red[base + i]     = a00[i] + a01[i] + a02[i];
                red[base + 4 + i] = a10[i] + a11[i] + a12[i];
            }
        }
        __syncthreads();

        // Group 0: reduce + epilogue.
        if (g == 0) {
            const float* red = (const float*)&sm[R_RED];
            const int base = (wq * 32 + lane) * 8;
            const size_t pb = (size_t)t * (B_ * H2);
            const size_t tb = (size_t)t * BH_;
#pragma unroll
            for (int nt = 0; nt < 2; nt++) {
                float ac[4];
                if (nt == 0) {
#pragma unroll
                    for (int i = 0; i < 4; i++)
                        ac[i] = a00[i] + a01[i] + a02[i] + red[base + i];
                } else {
#pragma unroll
                    for (int i = 0; i < 4; i++)
                        ac[i] = a10[i] + a11[i] + a12[i] + red[base + 4 + i];
                }
                const int col = n0 + wn + nt * 8 + 2 * qid;
                const int r0 = m0 + wm + grp;
                const float v00 = fast_tanh(ac[0] + pre[nt][0].x);
                const float v01 = fast_tanh(ac[1] + pre[nt][0].y);
                const float v10 = fast_tanh(ac[2] + pre[nt][1].x);
                const float v11 = fast_tanh(ac[3] + pre[nt][1].y);
                uint32_t hi0, lo0, hi1, lo1;
                splitpack(v00, v01, hi0, lo0);
                splitpack(v10, v11, hi1, lo1);
                pohi[pb + (size_t)r0 * H2 + (col >> 1)] = hi0;
                polo[pb + (size_t)r0 * H2 + (col >> 1)] = lo0;
                pohi[pb + (size_t)(r0 + 8) * H2 + (col >> 1)] = hi1;
                polo[pb + (size_t)(r0 + 8) * H2 + (col >> 1)] = lo1;
                if (Yout) {
                    float2 a = { v00, v01 }, b = { v10, v11 };
                    *(float2*)&Yout[tb + (size_t)r0 * H_ + col] = a;
                    *(float2*)&Yout[tb + (size_t)(r0 + 8) * H_ + col] = b;
                }
                if (t == T_ - 1) {
                    float2 a = { v00, v01 }, b = { v10, v11 };
                    *(float2*)&hn[(size_t)r0 * H_ + col] = a;
                    *(float2*)&hn[(size_t)(r0 + 8) * H_ + col] = b;
                }
            }
        }

        // Per-m-group barrier (32 CTAs).
        if (t < T_ - 1) {
            __syncthreads();
            if (tid == 0) {
                __threadfence();
                const unsigned int old = atomicAdd(&g_cnt4[mg], 1u);
                if (old == 31u) {
                    atomicExch(&g_cnt4[mg], 0u);
                    __threadfence();
                    atomicAdd(&g_gen4[mg], 1u);
                } else {
                    const unsigned int target = gen0 + (unsigned int)t + 1u;
                    while (*(volatile unsigned int*)&g_gen4[mg] < target) __nanosleep(32);
                }
                __threadfence();
            }
            __syncthreads();
        }
    }
}

// ---------------------------------------------------------------------------
extern "C" void kernel_launch(void* const* d_in, const int* in_sizes, int n_in,
                              void* d_out, int out_size)
{
    const float* inputs = (const float*)d_in[0];
    const float* hxs    = (const float*)d_in[1];
    const float* W_ih   = (const float*)d_in[2];
    const float* b_ih   = (const float*)d_in[3];
    const float* W_hh   = (const float*)d_in[4];
    const float* b_hh   = (const float*)d_in[5];
    float* out = (float*)d_out;

    float* P;
    uint32_t *xhi0, *xlo0, *xhi1, *xlo1, *uihi, *uilo, *whhi, *whlo, *hxhi, *hxlo;
    cudaGetSymbolAddress((void**)&P, g_P);
    cudaGetSymbolAddress((void**)&xhi0, g_xhi0);
    cudaGetSymbolAddress((void**)&xlo0, g_xlo0);
    cudaGetSymbolAddress((void**)&xhi1, g_xhi1);
    cudaGetSymbolAddress((void**)&xlo1, g_xlo1);
    cudaGetSymbolAddress((void**)&uihi, g_uihi);
    cudaGetSymbolAddress((void**)&uilo, g_uilo);
    cudaGetSymbolAddress((void**)&whhi, g_whhi);
    cudaGetSymbolAddress((void**)&whlo, g_whlo);
    cudaGetSymbolAddress((void**)&hxhi, g_hxhi);
    cudaGetSymbolAddress((void**)&hxlo, g_hxlo);

    cudaFuncSetAttribute(proj_kernel,  cudaFuncAttributeMaxDynamicSharedMemorySize, P_SMEM_BYTES);
    cudaFuncSetAttribute(recur_kernel, cudaFuncAttributeMaxDynamicSharedMemorySize, R_SMEM_BYTES);

    split_w_kernel<<<LHH2 / 256, 256>>>(W_ih, W_hh);
    split_x_kernel<<<(TB_ * H2) / 256, 256>>>(inputs);
    split_hx_kernel<<<(L_ * B_ * H2) / 256, 256>>>(hxs);

    uint32_t* xin_hi[2] = { xhi0, xhi1 };
    uint32_t* xin_lo[2] = { xlo0, xlo1 };

    const dim3 proj_grid(H_ / 64, TB_ / 128);   // (16, 256)
    const dim3 rec_grid(H_ / 32, B_ / 32);      // (32, 4) = 128 CTAs

    for (int l = 0; l < L_; l++) {
        const int pin = l & 1, pout = pin ^ 1;
        const size_t wo = (size_t)l * H_ * H2;

        proj_kernel<<<proj_grid, 256, P_SMEM_BYTES>>>(
            xin_hi[pin], xin_lo[pin], uihi + wo, uilo + wo,
            b_ih + (size_t)l * H_, b_hh + (size_t)l * H_, P);

        recur_kernel<<<rec_grid, 256, R_SMEM_BYTES>>>(
            hxhi + (size_t)l * (B_ * H2), hxlo + (size_t)l * (B_ * H2),
            whhi + wo, whlo + wo, P,
            xin_hi[pout], xin_lo[pout],
            (l == L_ - 1) ? out : nullptr,
            out + (size_t)TBH_ + (size_t)l * BH_);
    }
}

// round 12
// speedup vs baseline: 3.9837x; 1.0687x over previous
#include <cuda_runtime.h>
#include <cuda_bf16.h>
#include <cstdint>
#include <math.h>

#define T_ 256
#define B_ 128
#define H_ 1024
#define H2 512                    /* H/2 packed u32 pairs */
#define L_ 4
#define TB_ 32768
#define BH_ 131072
#define TBH_ 33554432
#define LHH2 (L_ * H_ * H2)       /* 2097152 */

// ---------------------------------------------------------------------------
// Device globals (allocation-free scratch)
// ---------------------------------------------------------------------------
__device__ float g_P[TBH_];
__device__ uint32_t g_xhi0[TB_ * H2];
__device__ uint32_t g_xlo0[TB_ * H2];
__device__ uint32_t g_xhi1[TB_ * H2];
__device__ uint32_t g_xlo1[TB_ * H2];
__device__ uint32_t g_uihi[LHH2], g_uilo[LHH2];
__device__ uint32_t g_whhi[LHH2], g_whlo[LHH2];
__device__ uint32_t g_hxhi[L_ * B_ * H2], g_hxlo[L_ * B_ * H2];
__device__ unsigned int g_cnt4[4] = {0, 0, 0, 0};   // monotonic, never reset
__device__ unsigned int g_gen4[4] = {0, 0, 0, 0};   // invariant: cnt == 32*gen

// ---------------------------------------------------------------------------
// Helpers
// ---------------------------------------------------------------------------
__device__ __forceinline__ uint32_t smem_u32(const void* p) {
    uint32_t a;
    asm("{ .reg .u64 t; cvta.to.shared.u64 t, %1; cvt.u32.u64 %0, t; }" : "=r"(a) : "l"(p));
    return a;
}
__device__ __forceinline__ void splitpack(float x0, float x1, uint32_t& hi, uint32_t& lo) {
    __nv_bfloat16 h0 = __float2bfloat16(x0);
    __nv_bfloat16 h1 = __float2bfloat16(x1);
    __nv_bfloat16 l0 = __float2bfloat16(x0 - __bfloat162float(h0));
    __nv_bfloat16 l1 = __float2bfloat16(x1 - __bfloat162float(h1));
    hi = (uint32_t)__bfloat16_as_ushort(h0) | ((uint32_t)__bfloat16_as_ushort(h1) << 16);
    lo = (uint32_t)__bfloat16_as_ushort(l0) | ((uint32_t)__bfloat16_as_ushort(l1) << 16);
}
__device__ __forceinline__ void mma16(float* d, const uint32_t* a, uint32_t b0, uint32_t b1) {
    asm volatile("mma.sync.aligned.m16n8k16.row.col.f32.bf16.bf16.f32 "
                 "{%0,%1,%2,%3}, {%4,%5,%6,%7}, {%8,%9}, {%0,%1,%2,%3};"
                 : "+f"(d[0]), "+f"(d[1]), "+f"(d[2]), "+f"(d[3])
                 : "r"(a[0]), "r"(a[1]), "r"(a[2]), "r"(a[3]), "r"(b0), "r"(b1));
}
#define LDSM4(r, addr) \
    asm volatile("ldmatrix.sync.aligned.m8n8.x4.shared.b16 {%0,%1,%2,%3}, [%4];" \
                 : "=r"((r)[0]), "=r"((r)[1]), "=r"((r)[2]), "=r"((r)[3]) : "r"(addr))
#define CP_ASYNC16(dst_u32, src_ptr) \
    asm volatile("cp.async.ca.shared.global [%0], [%1], 16;" \
                 :: "r"(dst_u32), "l"(src_ptr) : "memory")
#define CP_COMMIT() asm volatile("cp.async.commit_group;" ::: "memory")
#define CP_WAIT2()  asm volatile("cp.async.wait_group 2;" ::: "memory")
#define CP_WAIT1()  asm volatile("cp.async.wait_group 1;" ::: "memory")
#define CP_WAIT0()  asm volatile("cp.async.wait_group 0;" ::: "memory")
#define BAR_SYNC(id, cnt) \
    asm volatile("bar.sync %0, %1;" :: "r"(id), "r"(cnt) : "memory")

__device__ __forceinline__ unsigned atom_add_acqrel(unsigned* p, unsigned v) {
    unsigned old;
    asm volatile("atom.add.acq_rel.gpu.global.u32 %0, [%1], %2;"
                 : "=r"(old) : "l"(p), "r"(v) : "memory");
    return old;
}
__device__ __forceinline__ void red_add_release(unsigned* p) {
    asm volatile("red.add.release.gpu.global.u32 [%0], 1;" :: "l"(p) : "memory");
}
__device__ __forceinline__ unsigned ld_acquire(const unsigned* p) {
    unsigned v;
    asm volatile("ld.acquire.gpu.global.u32 %0, [%1];" : "=r"(v) : "l"(p) : "memory");
    return v;
}
__device__ __forceinline__ float fast_tanh(float x) {
    const float e = __expf(2.0f * x);
    return 1.0f - __fdividef(2.0f, e + 1.0f);
}

// ---------------------------------------------------------------------------
// One-time splits
// ---------------------------------------------------------------------------
__global__ __launch_bounds__(256)
void split_w_kernel(const float* __restrict__ Wih, const float* __restrict__ Whh)
{
    const size_t i = (size_t)blockIdx.x * 256 + threadIdx.x;
    uint32_t hi, lo;
    splitpack(Wih[2 * i], Wih[2 * i + 1], hi, lo);
    g_uihi[i] = hi; g_uilo[i] = lo;
    splitpack(Whh[2 * i], Whh[2 * i + 1], hi, lo);
    g_whhi[i] = hi; g_whlo[i] = lo;
}
__global__ __launch_bounds__(256)
void split_x_kernel(const float* __restrict__ X)
{
    const size_t i = (size_t)blockIdx.x * 256 + threadIdx.x;
    uint32_t hi, lo;
    splitpack(X[2 * i], X[2 * i + 1], hi, lo);
    g_xhi0[i] = hi; g_xlo0[i] = lo;
}
__global__ __launch_bounds__(256)
void split_hx_kernel(const float* __restrict__ hx)
{
    const size_t i = (size_t)blockIdx.x * 256 + threadIdx.x;
    uint32_t hi, lo;
    splitpack(hx[2 * i], hx[2 * i + 1], hi, lo);
    g_hxhi[i] = hi; g_hxlo[i] = lo;
}

// ---------------------------------------------------------------------------
// Input projection (unchanged from R8): P = X @ W^T + bi + bh.
// ---------------------------------------------------------------------------
#define P_STR 20
#define P_SAHI 0
#define P_SALO 2560
#define P_SBHI 5120
#define P_SBLO 6400
#define P_SMEM_BYTES (7680u * 4u)

__global__ __launch_bounds__(256, 2)
void proj_kernel(const uint32_t* __restrict__ Xhi, const uint32_t* __restrict__ Xlo,
                 const uint32_t* __restrict__ Whi_, const uint32_t* __restrict__ Wlo_,
                 const float* __restrict__ bi, const float* __restrict__ bhh,
                 float* __restrict__ P)
{
    extern __shared__ uint32_t sm[];
    const uint32_t smb = smem_u32(sm);
    const int tid = threadIdx.x, wid = tid >> 5, lane = tid & 31;
    const int grp = lane >> 2, qid = lane & 3;
    const int m0 = blockIdx.y * 128, n0 = blockIdx.x * 64;
    const int wm = (wid >> 1) * 32, wn = (wid & 1) * 32;

    const int arow_f = (lane & 7) + ((lane >> 3) & 1) * 8;
    const uint32_t akh = (lane >> 4) * 4;
    const uint32_t aoff0 = (uint32_t)(wm + arow_f) * P_STR + akh;
    const uint32_t aoff1 = (uint32_t)(wm + 16 + arow_f) * P_STR + akh;
    const int mB = lane >> 3;
    const int brow_f = (mB >> 1) * 8 + (lane & 7);
    const uint32_t bkh = (uint32_t)(mB & 1) * 4;
    const uint32_t boff0 = (uint32_t)(wn + brow_f) * P_STR + bkh;
    const uint32_t boff1 = (uint32_t)(wn + 16 + brow_f) * P_STR + bkh;

    const int arow = tid >> 1, acg = (tid & 1) * 8;
    const int brow = tid >> 2, bcg = (tid & 3) * 4;

    const uint32_t* Ah = Xhi  + (size_t)(m0 + arow) * H2 + acg;
    const uint32_t* Al = Xlo  + (size_t)(m0 + arow) * H2 + acg;
    const uint32_t* Bh = Whi_ + (size_t)(n0 + brow) * H2 + bcg;
    const uint32_t* Bl = Wlo_ + (size_t)(n0 + brow) * H2 + bcg;

    float acc[2][4][4];
#pragma unroll
    for (int mt = 0; mt < 2; mt++)
#pragma unroll
        for (int nt = 0; nt < 4; nt++)
#pragma unroll
            for (int i = 0; i < 4; i++) acc[mt][nt][i] = 0.0f;

    uint4 rah0 = *(const uint4*)Ah, rah1 = *(const uint4*)(Ah + 4);
    uint4 ral0 = *(const uint4*)Al, ral1 = *(const uint4*)(Al + 4);
    uint4 rbh  = *(const uint4*)Bh, rbl  = *(const uint4*)Bl;

    for (int kb2 = 0; kb2 < H2; kb2 += 16) {
        __syncthreads();
        *(uint4*)&sm[P_SAHI + arow * P_STR + acg]     = rah0;
        *(uint4*)&sm[P_SAHI + arow * P_STR + acg + 4] = rah1;
        *(uint4*)&sm[P_SALO + arow * P_STR + acg]     = ral0;
        *(uint4*)&sm[P_SALO + arow * P_STR + acg + 4] = ral1;
        *(uint4*)&sm[P_SBHI + brow * P_STR + bcg]     = rbh;
        *(uint4*)&sm[P_SBLO + brow * P_STR + bcg]     = rbl;
        __syncthreads();
        if (kb2 + 16 < H2) {
            rah0 = *(const uint4*)(Ah + kb2 + 16); rah1 = *(const uint4*)(Ah + kb2 + 20);
            ral0 = *(const uint4*)(Al + kb2 + 16); ral1 = *(const uint4*)(Al + kb2 + 20);
            rbh  = *(const uint4*)(Bh + kb2 + 16); rbl  = *(const uint4*)(Bl + kb2 + 16);
        }
#pragma unroll
        for (int kk = 0; kk < 2; kk++) {
            const uint32_t kb8 = kk * 8;
            uint32_t ah0[4], ah1[4], al0[4], al1[4];
            uint32_t bh01[4], bh23[4], bl01[4], bl23[4];
            LDSM4(ah0, smb + 4 * (P_SAHI + aoff0 + kb8));
            LDSM4(ah1, smb + 4 * (P_SAHI + aoff1 + kb8));
            LDSM4(al0, smb + 4 * (P_SALO + aoff0 + kb8));
            LDSM4(al1, smb + 4 * (P_SALO + aoff1 + kb8));
            LDSM4(bh01, smb + 4 * (P_SBHI + boff0 + kb8));
            LDSM4(bh23, smb + 4 * (P_SBHI + boff1 + kb8));
            LDSM4(bl01, smb + 4 * (P_SBLO + boff0 + kb8));
            LDSM4(bl23, smb + 4 * (P_SBLO + boff1 + kb8));
#pragma unroll
            for (int nt = 0; nt < 4; nt++) {
                const uint32_t* bhp = (nt < 2) ? bh01 : bh23;
                const uint32_t* blp = (nt < 2) ? bl01 : bl23;
                const int o = (nt & 1) * 2;
                mma16(acc[0][nt], ah0, bhp[o], bhp[o + 1]);
                mma16(acc[1][nt], ah1, bhp[o], bhp[o + 1]);
                mma16(acc[0][nt], ah0, blp[o], blp[o + 1]);
                mma16(acc[1][nt], ah1, blp[o], blp[o + 1]);
                mma16(acc[0][nt], al0, bhp[o], bhp[o + 1]);
                mma16(acc[1][nt], al1, bhp[o], bhp[o + 1]);
            }
        }
    }

#pragma unroll
    for (int mt = 0; mt < 2; mt++) {
#pragma unroll
        for (int nt = 0; nt < 4; nt++) {
            const int col = n0 + wn + nt * 8 + 2 * qid;
            const float bx = bi[col] + bhh[col];
            const float by = bi[col + 1] + bhh[col + 1];
            const int r0 = m0 + wm + mt * 16 + grp;
            float2 v0 = { acc[mt][nt][0] + bx, acc[mt][nt][1] + by };
            float2 v1 = { acc[mt][nt][2] + bx, acc[mt][nt][3] + by };
            *(float2*)&P[(size_t)r0 * H_ + col] = v0;
            *(float2*)&P[(size_t)(r0 + 8) * H_ + col] = v1;
        }
    }
}

// ---------------------------------------------------------------------------
// Persistent recurrence, K-split across two warp groups + cp.async A pipeline.
// Grid (32 n-tiles, 4 m-groups) = 128 CTAs, 256 thr (8 warps).
// Per group: 4-stage cp.async ring for A chunks, named-barrier visibility.
// W stripe resident in smem across all steps.
// ---------------------------------------------------------------------------
#define R_WSTR 516
#define R_ASTR 36
#define R_WHI 0
#define R_WLO 16512
#define R_ABUF 33024
#define R_ABUFSZ 2304            /* per stage: hi 1152 + lo 1152 */
#define R_RED (R_ABUF + 8 * R_ABUFSZ)       /* 4 stages x 2 groups */
#define R_SMEM_U32 (R_RED + 1024)
#define R_SMEM_BYTES (R_SMEM_U32 * 4u)      /* 209920 B */

__global__ __launch_bounds__(256, 1)
void recur_kernel(const uint32_t* __restrict__ hxhi, const uint32_t* __restrict__ hxlo,
                  const uint32_t* __restrict__ Whi_, const uint32_t* __restrict__ Wlo_,
                  const float* __restrict__ P,
                  uint32_t* __restrict__ pohi, uint32_t* __restrict__ polo,
                  float* __restrict__ Yout,
                  float* __restrict__ hn)
{
    extern __shared__ uint32_t sm[];
    const uint32_t smb = smem_u32(sm);
    __shared__ unsigned int s_gen;

    const int tid = threadIdx.x, wid = tid >> 5, lane = tid & 31;
    const int grp = lane >> 2, qid = lane & 3;
    const int n0 = blockIdx.x * 32, mg = blockIdx.y, m0 = mg * 32;
    const int g = wid >> 2;
    const int wq = wid & 3;
    const int wm = (wq >> 1) * 16, wn = (wq & 1) * 16;
    const int gbase = g * 256;

    const uint32_t aoff = (uint32_t)(wm + (lane & 7) + ((lane >> 3) & 1) * 8) * R_ASTR
                        + (lane >> 4) * 4;
    const int mB = lane >> 3;
    const uint32_t boff = (uint32_t)(wn + (mB >> 1) * 8 + (lane & 7)) * R_WSTR
                        + (uint32_t)(mB & 1) * 4;

    // Stage W stripe.
    for (int idx = tid * 4; idx < 32 * H2; idx += 256 * 4) {
        const int r = idx >> 9, c = idx & (H2 - 1);
        *(uint4*)&sm[R_WHI + r * R_WSTR + c] = *(const uint4*)&Whi_[(size_t)(n0 + r) * H2 + c];
        *(uint4*)&sm[R_WLO + r * R_WSTR + c] = *(const uint4*)&Wlo_[(size_t)(n0 + r) * H2 + c];
    }
    if (tid == 0) s_gen = ld_acquire(&g_gen4[mg]);
    __syncthreads();
    const unsigned int gen0 = s_gen;

    const int ltid = tid & 127;
    const int lrow = ltid >> 2, lcg = (ltid & 3) * 8;
    // smem dst offsets (u32 units) for this thread's cp.async, per stage.
    const uint32_t dst_hi = (uint32_t)(R_ABUF + g * 4 * R_ABUFSZ) + (uint32_t)lrow * R_ASTR + lcg;
    const uint32_t dst_lo = dst_hi + 1152;

    // P prefetch for t=0 (group 0 only).
    float2 pre[2][2];
    if (g == 0) {
#pragma unroll
        for (int nt = 0; nt < 2; nt++) {
            const int col = n0 + wn + nt * 8 + 2 * qid;
            const int r0 = m0 + wm + grp;
            pre[nt][0] = *(const float2*)&P[(size_t)r0 * H_ + col];
            pre[nt][1] = *(const float2*)&P[(size_t)(r0 + 8) * H_ + col];
        }
    }

    for (int t = 0; t < T_; t++) {
        const uint32_t* Ahp = t ? (pohi + (size_t)(t - 1) * (B_ * H2)) : hxhi;
        const uint32_t* Alp = t ? (polo + (size_t)(t - 1) * (B_ * H2)) : hxlo;
        const uint32_t* Ah = Ahp + (size_t)(m0 + lrow) * H2 + gbase + lcg;
        const uint32_t* Al = Alp + (size_t)(m0 + lrow) * H2 + gbase + lcg;

        // Issue chunks 0..2 into stages 0..2.
#pragma unroll
        for (int s = 0; s < 3; s++) {
            const uint32_t d = 4 * (dst_hi + (uint32_t)s * R_ABUFSZ);
            const uint32_t dl = 4 * (dst_lo + (uint32_t)s * R_ABUFSZ);
            CP_ASYNC16(smb + d,           Ah + s * 32);
            CP_ASYNC16(smb + d + 16,      Ah + s * 32 + 4);
            CP_ASYNC16(smb + dl,          Al + s * 32);
            CP_ASYNC16(smb + dl + 16,     Al + s * 32 + 4);
            CP_COMMIT();
        }

        float a00[4] = {0,0,0,0}, a01[4] = {0,0,0,0}, a02[4] = {0,0,0,0};
        float a10[4] = {0,0,0,0}, a11[4] = {0,0,0,0}, a12[4] = {0,0,0,0};

#pragma unroll
        for (int c = 0; c < 8; c++) {
            if (c <= 5) { CP_WAIT2(); } else if (c == 6) { CP_WAIT1(); } else { CP_WAIT0(); }
            BAR_SYNC(1 + g, 128);

            const uint32_t abase = smb + 4 * (R_ABUF + (g * 4 + (c & 3)) * R_ABUFSZ + aoff);
            const uint32_t kcb = gbase + c * 32;
#pragma unroll
            for (int kk = 0; kk < 4; kk++) {
                const uint32_t kb8 = kk * 8;
                uint32_t ah[4], al[4], bh[4], bl[4];
                LDSM4(ah, abase + 4 * kb8);
                LDSM4(al, abase + 4 * (1152 + kb8));
                LDSM4(bh, smb + 4 * (R_WHI + boff + kcb + kb8));
                LDSM4(bl, smb + 4 * (R_WLO + boff + kcb + kb8));
                mma16(a00, ah, bh[0], bh[1]);
                mma16(a10, ah, bh[2], bh[3]);
                mma16(a01, ah, bl[0], bl[1]);
                mma16(a11, ah, bl[2], bl[3]);
                mma16(a02, al, bh[0], bh[1]);
                mma16(a12, al, bh[2], bh[3]);
            }
            if (c < 5) {
                const int s = (c + 3) & 3;
                const uint32_t d  = 4 * (dst_hi + (uint32_t)s * R_ABUFSZ);
                const uint32_t dl = 4 * (dst_lo + (uint32_t)s * R_ABUFSZ);
                CP_ASYNC16(smb + d,       Ah + (c + 3) * 32);
                CP_ASYNC16(smb + d + 16,  Ah + (c + 3) * 32 + 4);
                CP_ASYNC16(smb + dl,      Al + (c + 3) * 32);
                CP_ASYNC16(smb + dl + 16, Al + (c + 3) * 32 + 4);
                CP_COMMIT();
            }
        }

        // Group 1 publishes partials; full sync; group 0 reduces + epilogue.
        if (g == 1) {
            float* red = (float*)&sm[R_RED];
            const int base = (wq * 32 + lane) * 8;
#pragma unroll
            for (int i = 0; i < 4; i++) {
                red[base + i]     = a00[i] + a01[i] + a02[i];
                red[base + 4 + i] = a10[i] + a11[i] + a12[i];
            }
        }
        __syncthreads();

        if (g == 0) {
            const float* red = (const float*)&sm[R_RED];
            const int base = (wq * 32 + lane) * 8;
            const size_t pb = (size_t)t * (B_ * H2);
            const size_t tb = (size_t)t * BH_;
#pragma unroll
            for (int nt = 0; nt < 2; nt++) {
                float ac[4];
                if (nt == 0) {
#pragma unroll
                    for (int i = 0; i < 4; i++)
                        ac[i] = a00[i] + a01[i] + a02[i] + red[base + i];
                } else {
#pragma unroll
                    for (int i = 0; i < 4; i++)
                        ac[i] = a10[i] + a11[i] + a12[i] + red[base + 4 + i];
                }
                const int col = n0 + wn + nt * 8 + 2 * qid;
                const int r0 = m0 + wm + grp;
                const float v00 = fast_tanh(ac[0] + pre[nt][0].x);
                const float v01 = fast_tanh(ac[1] + pre[nt][0].y);
                const float v10 = fast_tanh(ac[2] + pre[nt][1].x);
                const float v11 = fast_tanh(ac[3] + pre[nt][1].y);
                uint32_t hi0, lo0, hi1, lo1;
                splitpack(v00, v01, hi0, lo0);
                splitpack(v10, v11, hi1, lo1);
                pohi[pb + (size_t)r0 * H2 + (col >> 1)] = hi0;
                polo[pb + (size_t)r0 * H2 + (col >> 1)] = lo0;
                pohi[pb + (size_t)(r0 + 8) * H2 + (col >> 1)] = hi1;
                polo[pb + (size_t)(r0 + 8) * H2 + (col >> 1)] = lo1;
                if (Yout) {
                    float2 a = { v00, v01 }, b = { v10, v11 };
                    *(float2*)&Yout[tb + (size_t)r0 * H_ + col] = a;
                    *(float2*)&Yout[tb + (size_t)(r0 + 8) * H_ + col] = b;
                }
                if (t == T_ - 1) {
                    float2 a = { v00, v01 }, b = { v10, v11 };
                    *(float2*)&hn[(size_t)r0 * H_ + col] = a;
                    *(float2*)&hn[(size_t)(r0 + 8) * H_ + col] = b;
                }
            }
            // Prefetch P for step t+1 (hidden behind the grid barrier).
            if (t + 1 < T_) {
                const size_t tb1 = (size_t)(t + 1) * BH_;
#pragma unroll
                for (int nt = 0; nt < 2; nt++) {
                    const int col = n0 + wn + nt * 8 + 2 * qid;
                    const int r0 = m0 + wm + grp;
                    pre[nt][0] = *(const float2*)&P[tb1 + (size_t)r0 * H_ + col];
                    pre[nt][1] = *(const float2*)&P[tb1 + (size_t)(r0 + 8) * H_ + col];
                }
            }
        }

        // Per-m-group grid barrier (32 CTAs), acq/rel, monotonic counters.
        if (t < T_ - 1) {
            __syncthreads();                       // h stores complete CTA-wide
            if (tid == 0) {
                const unsigned old = atom_add_acqrel(&g_cnt4[mg], 1u);
                if ((old & 31u) == 31u) {
                    red_add_release(&g_gen4[mg]);
                } else {
                    const unsigned target = gen0 + (unsigned)t + 1u;
                    while (ld_acquire(&g_gen4[mg]) < target) __nanosleep(32);
                }
            }
            __syncthreads();
        }
    }
}

// ---------------------------------------------------------------------------
extern "C" void kernel_launch(void* const* d_in, const int* in_sizes, int n_in,
                              void* d_out, int out_size)
{
    const float* inputs = (const float*)d_in[0];
    const float* hxs    = (const float*)d_in[1];
    const float* W_ih   = (const float*)d_in[2];
    const float* b_ih   = (const float*)d_in[3];
    const float* W_hh   = (const float*)d_in[4];
    const float* b_hh   = (const float*)d_in[5];
    float* out = (float*)d_out;

    float* P;
    uint32_t *xhi0, *xlo0, *xhi1, *xlo1, *uihi, *uilo, *whhi, *whlo, *hxhi, *hxlo;
    cudaGetSymbolAddress((void**)&P, g_P);
    cudaGetSymbolAddress((void**)&xhi0, g_xhi0);
    cudaGetSymbolAddress((void**)&xlo0, g_xlo0);
    cudaGetSymbolAddress((void**)&xhi1, g_xhi1);
    cudaGetSymbolAddress((void**)&xlo1, g_xlo1);
    cudaGetSymbolAddress((void**)&uihi, g_uihi);
    cudaGetSymbolAddress((void**)&uilo, g_uilo);
    cudaGetSymbolAddress((void**)&whhi, g_whhi);
    cudaGetSymbolAddress((void**)&whlo, g_whlo);
    cudaGetSymbolAddress((void**)&hxhi, g_hxhi);
    cudaGetSymbolAddress((void**)&hxlo, g_hxlo);

    cudaFuncSetAttribute(proj_kernel,  cudaFuncAttributeMaxDynamicSharedMemorySize, P_SMEM_BYTES);
    cudaFuncSetAttribute(recur_kernel, cudaFuncAttributeMaxDynamicSharedMemorySize, R_SMEM_BYTES);

    split_w_kernel<<<LHH2 / 256, 256>>>(W_ih, W_hh);
    split_x_kernel<<<(TB_ * H2) / 256, 256>>>(inputs);
    split_hx_kernel<<<(L_ * B_ * H2) / 256, 256>>>(hxs);

    uint32_t* xin_hi[2] = { xhi0, xhi1 };
    uint32_t* xin_lo[2] = { xlo0, xlo1 };

    const dim3 proj_grid(H_ / 64, TB_ / 128);   // (16, 256)
    const dim3 rec_grid(H_ / 32, B_ / 32);      // (32, 4) = 128 CTAs

    for (int l = 0; l < L_; l++) {
        const int pin = l & 1, pout = pin ^ 1;
        const size_t wo = (size_t)l * H_ * H2;

        proj_kernel<<<proj_grid, 256, P_SMEM_BYTES>>>(
            xin_hi[pin], xin_lo[pin], uihi + wo, uilo + wo,
            b_ih + (size_t)l * H_, b_hh + (size_t)l * H_, P);

        recur_kernel<<<rec_grid, 256, R_SMEM_BYTES>>>(
            hxhi + (size_t)l * (B_ * H2), hxlo + (size_t)l * (B_ * H2),
            whhi + wo, whlo + wo, P,
            xin_hi[pout], xin_lo[pout],
            (l == L_ - 1) ? out : nullptr,
            out + (size_t)TBH_ + (size_t)l * BH_);
    }
}